// round 5
// baseline (speedup 1.0000x reference)
#include <cuda_runtime.h>
#include <cstdint>

// Problem constants
#define T_TOK   4096
#define D_MODEL 1024
#define DFF     2048
#define NROUTED 7
#define BM      128
#define BK      64
#define NTILES_M 104
#define R_MAX   (NTILES_M * BM)

// smem tile geometry: 128 rows x 256B (BK=64 fp32), stride 272B (conflict-free ldmatrix)
#define ROWB   272
#define TILEB  (128 * ROWB)          // 34816 B

// ---------------- scratch (static device globals; no allocations) -------------
__device__ float d_H[(size_t)R_MAX * DFF];            // hidden (tf32-rounded)
__device__ float d_X[(size_t)T_TOK * D_MODEL];        // x tf32-rounded
__device__ float d_wgT[(size_t)8 * DFF * D_MODEL];    // [E][N=DFF][K=D] tf32
__device__ float d_wuT[(size_t)8 * DFF * D_MODEL];
__device__ float d_wdT[(size_t)8 * D_MODEL * DFF];    // [E][N=D][K=DFF] tf32
__device__ int   d_tok[R_MAX];
__device__ float d_wrow[R_MAX];
__device__ int   d_off[8];
__device__ int   d_cnt[NROUTED];
__device__ int   d_cnt2[NROUTED];
__device__ int   d_topi[T_TOK * 2];
__device__ float d_topw[T_TOK * 2];

// ---------------- helpers ----------------------------------------------------
__device__ __forceinline__ uint32_t f2tf(float f) {
    uint32_t r;
    asm("cvt.rna.tf32.f32 %0, %1;" : "=r"(r) : "f"(f));
    return r;
}

__device__ __forceinline__ uint32_t smem_u32(const void* p) {
    uint32_t a;
    asm("{ .reg .u64 t; cvta.to.shared.u64 t, %1; cvt.u32.u64 %0, t; }"
        : "=r"(a) : "l"(p));
    return a;
}

__device__ __forceinline__ void mma8(float c[4], const uint32_t a[4], const uint32_t b[2]) {
    asm volatile(
        "mma.sync.aligned.m16n8k8.row.col.f32.tf32.tf32.f32 "
        "{%0,%1,%2,%3}, {%4,%5,%6,%7}, {%8,%9}, {%0,%1,%2,%3};\n"
        : "+f"(c[0]), "+f"(c[1]), "+f"(c[2]), "+f"(c[3])
        : "r"(a[0]), "r"(a[1]), "r"(a[2]), "r"(a[3]), "r"(b[0]), "r"(b[1]));
}

#define LDSM4(r0, r1, r2, r3, addr) \
    asm volatile("ldmatrix.sync.aligned.m8n8.x4.shared.b16 {%0,%1,%2,%3}, [%4];" \
                 : "=r"(r0), "=r"(r1), "=r"(r2), "=r"(r3) : "r"(addr))

// 256-byte 1D bulk copy, completion via mbarrier tx bytes (sm_90 standard PTX)
__device__ __forceinline__ void blkcp256(uint32_t dst, const float* src, uint32_t mbar) {
    asm volatile(
        "cp.async.bulk.shared::cluster.global.mbarrier::complete_tx::bytes "
        "[%0], [%1], 256, [%2];"
        :: "r"(dst), "l"(src), "r"(mbar) : "memory");
}

__device__ __forceinline__ void mbar_init(uint32_t addr, uint32_t cnt) {
    asm volatile("mbarrier.init.shared.b64 [%0], %1;" :: "r"(addr), "r"(cnt) : "memory");
}
__device__ __forceinline__ void mbar_expect(uint32_t addr, uint32_t bytes) {
    asm volatile("mbarrier.arrive.expect_tx.shared.b64 _, [%0], %1;"
                 :: "r"(addr), "r"(bytes) : "memory");
}
__device__ __forceinline__ void mbar_wait(uint32_t addr, uint32_t parity) {
    asm volatile(
        "{\n\t.reg .pred P;\n\t"
        "W%=:\n\t"
        "mbarrier.try_wait.parity.acquire.cta.shared::cta.b64 P, [%0], %1, 0x989680;\n\t"
        "@!P bra W%=;\n\t}"
        :: "r"(addr), "r"(parity) : "memory");
}

// ---------------- kernel 1: fused init + router --------------------------------
__global__ void init_router_kernel(const float* __restrict__ x,
                                   const float* __restrict__ rw,
                                   const float* __restrict__ rb,
                                   float* __restrict__ out) {
    int tid = threadIdx.x;
    // ---- router duty: blocks [0, 512), 8 warps = 8 tokens each ----
    if (blockIdx.x < 512) {
        int warp = tid >> 5, lane = tid & 31;
        int gw = blockIdx.x * 8 + warp;   // token id, < 4096
        const float* xr = x + (size_t)gw * D_MODEL;
        float acc[NROUTED];
#pragma unroll
        for (int j = 0; j < NROUTED; j++) acc[j] = 0.f;
        for (int k = lane; k < D_MODEL; k += 32) {
            float xv = xr[k];
            const float* w = rw + k * NROUTED;
#pragma unroll
            for (int j = 0; j < NROUTED; j++) acc[j] += xv * w[j];
        }
#pragma unroll
        for (int j = 0; j < NROUTED; j++) {
#pragma unroll
            for (int o = 16; o > 0; o >>= 1)
                acc[j] += __shfl_xor_sync(0xffffffffu, acc[j], o);
        }
        if (lane == 0) {
            float lg[NROUTED];
#pragma unroll
            for (int j = 0; j < NROUTED; j++) lg[j] = acc[j] + rb[j];
            int i1 = 0;
#pragma unroll
            for (int j = 1; j < NROUTED; j++) if (lg[j] > lg[i1]) i1 = j;
            int i2 = (i1 == 0) ? 1 : 0;
#pragma unroll
            for (int j = 0; j < NROUTED; j++)
                if (j != i1 && lg[j] > lg[i2]) i2 = j;
            float m  = fmaxf(lg[i1], lg[i2]);
            float e1 = expf(lg[i1] - m), e2 = expf(lg[i2] - m);
            float s  = e1 + e2;
            d_topi[gw * 2] = i1;  d_topi[gw * 2 + 1] = i2;
            d_topw[gw * 2] = e1 / s;  d_topw[gw * 2 + 1] = e2 / s;
            atomicAdd(&d_cnt[i1], 1);   // d_cnt zeroed by prior offsfill (or bss init)
            atomicAdd(&d_cnt[i2], 1);
        }
    }
    // ---- init duty: all blocks, grid-stride ----
    int stride = gridDim.x * blockDim.x;
    int i = blockIdx.x * blockDim.x + tid;
    for (int j = i; j < T_TOK * D_MODEL; j += stride) {
        out[j] = 0.f;
        d_X[j] = __uint_as_float(f2tf(x[j]));
    }
    for (int j = i; j < R_MAX; j += stride) {
        if (j < T_TOK) { d_tok[j] = j;  d_wrow[j] = 1.f; }
        else           { d_tok[j] = -1; d_wrow[j] = 0.f; }
    }
}

// ---------------- kernel 2: offsets + fill (single block) ----------------------
__global__ void offsfill_kernel() {
    int tid = threadIdx.x;
    if (tid == 0) {
        int base = T_TOK;
        for (int j = 0; j < NROUTED; j++) {
            d_off[j] = base;
            base += ((d_cnt[j] + BM - 1) / BM) * BM;
            d_cnt[j] = 0;   // reset for next replay
        }
        d_off[7] = base;
    }
    __syncthreads();
    for (int i = tid; i < T_TOK * 2; i += blockDim.x) {
        int t = i >> 1;
        int e = d_topi[i];
        float w = d_topw[i];
        int p = atomicAdd(&d_cnt2[e], 1);
        int r = d_off[e] + p;
        d_tok[r]  = t;
        d_wrow[r] = w;
    }
    __syncthreads();
    if (tid < NROUTED) d_cnt2[tid] = 0;   // reset for next replay
}

// ---------------- kernel 3: all weight transposes + tf32 round -----------------
__global__ void tr_all_kernel(const float* __restrict__ wg,
                              const float* __restrict__ wu,
                              const float* __restrict__ wd) {
    __shared__ float t[32][33];
    int z = blockIdx.z;
    const float* s; float* d; int R, C, e;
    if (z < 8)       { e = z;      s = wg; d = d_wgT; R = D_MODEL; C = DFF; }
    else if (z < 16) { e = z - 8;  s = wu; d = d_wuT; R = D_MODEL; C = DFF; }
    else             { e = z - 16; s = wd; d = d_wdT; R = DFF;     C = D_MODEL; }
    int c0 = blockIdx.x * 32, r0 = blockIdx.y * 32;
    if (c0 >= C || r0 >= R) return;
    s += (size_t)e * R * C;
    d += (size_t)e * R * C;
    int tx = threadIdx.x;
#pragma unroll
    for (int i = threadIdx.y; i < 32; i += 8)
        t[i][tx] = s[(size_t)(r0 + i) * C + c0 + tx];
    __syncthreads();
#pragma unroll
    for (int i = threadIdx.y; i < 32; i += 8)
        d[(size_t)(c0 + i) * R + r0 + tx] = __uint_as_float(f2tf(t[tx][i]));
}

__device__ __forceinline__ int tile_expert(int row0) {
    if (row0 < T_TOK) return 0;
    int e = 0;
#pragma unroll
    for (int j = 0; j < NROUTED; j++)
        if (row0 >= d_off[j] && row0 < d_off[j + 1]) e = j + 1;
    return e;
}

// ---------------- gemm1: BM=128 BN=128 BK=64, bulk-copy pipeline ----------------
#define G1_STG  (3 * TILEB)          // A + Bg + Bu per stage
#define G1_SMEM (2 * G1_STG)         // 208896 B

__global__ __launch_bounds__(512, 1) void gemm1_kernel() {
    int row0 = blockIdx.x * BM;
    if (row0 >= d_off[7]) return;
    int e = tile_expert(row0);
    const float* bg = d_wgT + (size_t)e * DFF * D_MODEL;
    const float* bu = d_wuT + (size_t)e * DFF * D_MODEL;
    int n0 = blockIdx.y * 128;

    extern __shared__ char raw[];
    uint32_t base = smem_u32(raw);
    __shared__ int stok[128];
    __shared__ __align__(8) uint64_t s_mb[2];

    int tid = threadIdx.x, warp = tid >> 5, lane = tid & 31;
    if (tid < 128) stok[tid] = d_tok[row0 + tid];
    uint32_t mb0 = smem_u32(&s_mb[0]), mb1 = smem_u32(&s_mb[1]);
    if (tid == 0) { mbar_init(mb0, 1); mbar_init(mb1, 1); }
    __syncthreads();

    int wm = (warp >> 2) * 32, wn = (warp & 3) * 32;

    // ldmatrix intra-tile offsets (bytes)
    int arow = 8 * ((lane >> 3) & 1) + (lane & 7);
    int acol = 4 * (lane >> 4);
    uint32_t aoff[2];
#pragma unroll
    for (int mi = 0; mi < 2; mi++)
        aoff[mi] = (uint32_t)((wm + mi * 16 + arow) * ROWB + acol * 4);
    int brow = 8 * (lane >> 4) + (lane & 7);
    int bcol = 4 * ((lane >> 3) & 1);
    uint32_t goff[2], uoff[2];
#pragma unroll
    for (int p = 0; p < 2; p++) {
        uint32_t o = (uint32_t)((wn + p * 16 + brow) * ROWB + bcol * 4);
        goff[p] = TILEB + o;
        uoff[p] = 2 * TILEB + o;
    }

    float accG[2][4][4], accU[2][4][4];
#pragma unroll
    for (int mi = 0; mi < 2; mi++)
#pragma unroll
        for (int ni = 0; ni < 4; ni++)
#pragma unroll
            for (int r = 0; r < 4; r++) { accG[mi][ni][r] = 0.f; accU[mi][ni][r] = 0.f; }

    const int KT = D_MODEL / BK;   // 16

    // prologue: chunk 0 -> stage 0 (warp 0 produces)
    if (warp == 0) {
        if (lane == 0) mbar_expect(mb0, 3u * 128u * 256u);
        __syncwarp();
#pragma unroll
        for (int j = 0; j < 4; j++) {
            int r = lane + j * 32;
            int tok = stok[r]; if (tok < 0) tok = 0;       // dead rows: dummy, discarded later
            blkcp256(base + r * ROWB,             d_X + (size_t)tok * D_MODEL, mb0);
            blkcp256(base + TILEB + r * ROWB,     bg + (size_t)(n0 + r) * D_MODEL, mb0);
            blkcp256(base + 2 * TILEB + r * ROWB, bu + (size_t)(n0 + r) * D_MODEL, mb0);
        }
    }

    for (int kt = 0; kt < KT; kt++) {
        __syncthreads();   // all warps done consuming stage (kt+1)&1 from iter kt-1
        if (warp == 0 && kt + 1 < KT) {
            int st = (kt + 1) & 1;
            int k0 = (kt + 1) * BK;
            uint32_t S = base + st * G1_STG;
            uint32_t mb = st ? mb1 : mb0;
            if (lane == 0) mbar_expect(mb, 3u * 128u * 256u);
            __syncwarp();
#pragma unroll
            for (int j = 0; j < 4; j++) {
                int r = lane + j * 32;
                int tok = stok[r]; if (tok < 0) tok = 0;
                blkcp256(S + r * ROWB,             d_X + (size_t)tok * D_MODEL + k0, mb);
                blkcp256(S + TILEB + r * ROWB,     bg + (size_t)(n0 + r) * D_MODEL + k0, mb);
                blkcp256(S + 2 * TILEB + r * ROWB, bu + (size_t)(n0 + r) * D_MODEL + k0, mb);
            }
        }
        mbar_wait((kt & 1) ? mb1 : mb0, (kt >> 1) & 1);

        uint32_t S = base + (kt & 1) * G1_STG;
#pragma unroll
        for (int kk = 0; kk < BK; kk += 8) {
            uint32_t a[2][4];
            LDSM4(a[0][0], a[0][1], a[0][2], a[0][3], S + aoff[0] + kk * 4);
            LDSM4(a[1][0], a[1][1], a[1][2], a[1][3], S + aoff[1] + kk * 4);
#pragma unroll
            for (int p = 0; p < 2; p++) {
                uint32_t g4[4], u4[4];
                LDSM4(g4[0], g4[1], g4[2], g4[3], S + goff[p] + kk * 4);
                LDSM4(u4[0], u4[1], u4[2], u4[3], S + uoff[p] + kk * 4);
                mma8(accG[0][2 * p],     a[0], g4 + 0);
                mma8(accG[1][2 * p],     a[1], g4 + 0);
                mma8(accG[0][2 * p + 1], a[0], g4 + 2);
                mma8(accG[1][2 * p + 1], a[1], g4 + 2);
                mma8(accU[0][2 * p],     a[0], u4 + 0);
                mma8(accU[1][2 * p],     a[1], u4 + 0);
                mma8(accU[0][2 * p + 1], a[0], u4 + 2);
                mma8(accU[1][2 * p + 1], a[1], u4 + 2);
            }
        }
    }

    // epilogue: H = tf32_round(silu(g) * u)
#pragma unroll
    for (int mi = 0; mi < 2; mi++)
#pragma unroll
        for (int ni = 0; ni < 4; ni++)
#pragma unroll
            for (int rr = 0; rr < 4; rr++) {
                int rl = wm + mi * 16 + ((tid & 31) >> 2) + ((rr >= 2) ? 8 : 0);
                if (stok[rl] < 0) continue;
                int col = n0 + wn + ni * 8 + 2 * (tid & 3) + (rr & 1);
                float g = accG[mi][ni][rr], u = accU[mi][ni][rr];
                float h = (g / (1.f + __expf(-g))) * u;
                d_H[(size_t)(row0 + rl) * DFF + col] = __uint_as_float(f2tf(h));
            }
}

// ---------------- gemm2: down GEMM + weighted scatter-add ----------------------
#define G2_STG  (2 * TILEB)
#define G2_SMEM (2 * G2_STG)         // 139264 B

__global__ __launch_bounds__(512, 1) void gemm2_kernel(float* __restrict__ out) {
    int row0 = blockIdx.x * BM;
    if (row0 >= d_off[7]) return;
    int e = tile_expert(row0);
    const float* bw = d_wdT + (size_t)e * DFF * D_MODEL;
    int n0 = blockIdx.y * 128;

    extern __shared__ char raw[];
    uint32_t base = smem_u32(raw);
    __shared__ int stok[128];
    __shared__ float swt[128];
    __shared__ __align__(8) uint64_t s_mb[2];

    int tid = threadIdx.x, warp = tid >> 5, lane = tid & 31;
    if (tid < 128) { stok[tid] = d_tok[row0 + tid]; swt[tid] = d_wrow[row0 + tid]; }
    uint32_t mb0 = smem_u32(&s_mb[0]), mb1 = smem_u32(&s_mb[1]);
    if (tid == 0) { mbar_init(mb0, 1); mbar_init(mb1, 1); }
    __syncthreads();

    int wm = (warp >> 2) * 32, wn = (warp & 3) * 32;

    int arow = 8 * ((lane >> 3) & 1) + (lane & 7);
    int acol = 4 * (lane >> 4);
    uint32_t aoff[2];
#pragma unroll
    for (int mi = 0; mi < 2; mi++)
        aoff[mi] = (uint32_t)((wm + mi * 16 + arow) * ROWB + acol * 4);
    int brow = 8 * (lane >> 4) + (lane & 7);
    int bcol = 4 * ((lane >> 3) & 1);
    uint32_t boff[2];
#pragma unroll
    for (int p = 0; p < 2; p++)
        boff[p] = TILEB + (uint32_t)((wn + p * 16 + brow) * ROWB + bcol * 4);

    float acc[2][4][4];
#pragma unroll
    for (int mi = 0; mi < 2; mi++)
#pragma unroll
        for (int ni = 0; ni < 4; ni++)
#pragma unroll
            for (int r = 0; r < 4; r++) acc[mi][ni][r] = 0.f;

    const int KT = DFF / BK;   // 32

    if (warp == 0) {
        if (lane == 0) mbar_expect(mb0, 2u * 128u * 256u);
        __syncwarp();
#pragma unroll
        for (int j = 0; j < 4; j++) {
            int r = lane + j * 32;
            blkcp256(base + r * ROWB,         d_H + (size_t)(row0 + r) * DFF, mb0);
            blkcp256(base + TILEB + r * ROWB, bw + (size_t)(n0 + r) * DFF, mb0);
        }
    }

    for (int kt = 0; kt < KT; kt++) {
        __syncthreads();
        if (warp == 0 && kt + 1 < KT) {
            int st = (kt + 1) & 1;
            int k0 = (kt + 1) * BK;
            uint32_t S = base + st * G2_STG;
            uint32_t mb = st ? mb1 : mb0;
            if (lane == 0) mbar_expect(mb, 2u * 128u * 256u);
            __syncwarp();
#pragma unroll
            for (int j = 0; j < 4; j++) {
                int r = lane + j * 32;
                blkcp256(S + r * ROWB,         d_H + (size_t)(row0 + r) * DFF + k0, mb);
                blkcp256(S + TILEB + r * ROWB, bw + (size_t)(n0 + r) * DFF + k0, mb);
            }
        }
        mbar_wait((kt & 1) ? mb1 : mb0, (kt >> 1) & 1);

        uint32_t S = base + (kt & 1) * G2_STG;
#pragma unroll
        for (int kk = 0; kk < BK; kk += 8) {
            uint32_t a[2][4];
            LDSM4(a[0][0], a[0][1], a[0][2], a[0][3], S + aoff[0] + kk * 4);
            LDSM4(a[1][0], a[1][1], a[1][2], a[1][3], S + aoff[1] + kk * 4);
#pragma unroll
            for (int p = 0; p < 2; p++) {
                uint32_t b4[4];
                LDSM4(b4[0], b4[1], b4[2], b4[3], S + boff[p] + kk * 4);
                mma8(acc[0][2 * p],     a[0], b4 + 0);
                mma8(acc[1][2 * p],     a[1], b4 + 0);
                mma8(acc[0][2 * p + 1], a[0], b4 + 2);
                mma8(acc[1][2 * p + 1], a[1], b4 + 2);
            }
        }
    }

#pragma unroll
    for (int mi = 0; mi < 2; mi++)
#pragma unroll
        for (int ni = 0; ni < 4; ni++)
#pragma unroll
            for (int rr = 0; rr < 4; rr++) {
                int rl = wm + mi * 16 + ((tid & 31) >> 2) + ((rr >= 2) ? 8 : 0);
                int tok = stok[rl];
                if (tok < 0) continue;
                int col = n0 + wn + ni * 8 + 2 * (tid & 3) + (rr & 1);
                atomicAdd(out + (size_t)tok * D_MODEL + col, swt[rl] * acc[mi][ni][rr]);
            }
}

// ---------------- launch -------------------------------------------------------
extern "C" void kernel_launch(void* const* d_in, const int* in_sizes, int n_in,
                              void* d_out, int out_size) {
    const float* x  = (const float*)d_in[0];
    const float* rw = (const float*)d_in[1];
    const float* rb = (const float*)d_in[2];
    const float* wg = (const float*)d_in[3];
    const float* wu = (const float*)d_in[4];
    const float* wd = (const float*)d_in[5];
    float* out = (float*)d_out;
    (void)in_sizes; (void)n_in; (void)out_size;

    static bool attr_done = false;
    if (!attr_done) {
        cudaFuncSetAttribute(gemm1_kernel, cudaFuncAttributeMaxDynamicSharedMemorySize, G1_SMEM);
        cudaFuncSetAttribute(gemm2_kernel, cudaFuncAttributeMaxDynamicSharedMemorySize, G2_SMEM);
        attr_done = true;
    }

    // Launch order chosen so gemm1 is the 4th launch (ncu capture window).
    init_router_kernel<<<1024, 256>>>(x, rw, rb, out);
    offsfill_kernel<<<1, 1024>>>();
    tr_all_kernel<<<dim3(64, 64, 24), dim3(32, 8)>>>(wg, wu, wd);
    gemm1_kernel<<<dim3(NTILES_M, DFF / 128), 512, G1_SMEM>>>();
    gemm2_kernel<<<dim3(NTILES_M, D_MODEL / 128), 512, G2_SMEM>>>(out);
}

// round 6
// speedup vs baseline: 4.9738x; 4.9738x over previous
#include <cuda_runtime.h>
#include <cuda_fp16.h>
#include <cstdint>

// Problem constants
#define T_TOK   4096
#define D_MODEL 1024
#define DFF     2048
#define NROUTED 7
#define BM      128
#define BK      64
#define NTILES_M 104
#define R_MAX   (NTILES_M * BM)

// smem tile: 128 rows x 128B data (64 fp16), stride 144B -> conflict-free ldmatrix
#define ROWB   144
#define TILEB  (128 * ROWB)      // 18432 B

// ---------------- scratch (static device globals; no allocations) -------------
__device__ __half d_H[(size_t)R_MAX * DFF];           // hidden, fp16
__device__ __half d_X[(size_t)T_TOK * D_MODEL];       // x, fp16
__device__ __half d_wgT[(size_t)8 * DFF * D_MODEL];   // [E][N=DFF][K=D] fp16
__device__ __half d_wuT[(size_t)8 * DFF * D_MODEL];
__device__ __half d_wdT[(size_t)8 * D_MODEL * DFF];   // [E][N=D][K=DFF] fp16
__device__ int    d_tok[R_MAX];
__device__ float  d_wrow[R_MAX];
__device__ int    d_off[8];
__device__ int    d_cnt[NROUTED];
__device__ int    d_cnt2[NROUTED];
__device__ int    d_topi[T_TOK * 2];
__device__ float  d_topw[T_TOK * 2];

// ---------------- helpers ----------------------------------------------------
__device__ __forceinline__ uint32_t smem_u32(const void* p) {
    uint32_t a;
    asm("{ .reg .u64 t; cvta.to.shared.u64 t, %1; cvt.u32.u64 %0, t; }"
        : "=r"(a) : "l"(p));
    return a;
}

// fp16 tensor-core mma: D(f32) += A(f16) * B(f16)
__device__ __forceinline__ void hmma(float c[4], const uint32_t a[4], const uint32_t b[2]) {
    asm volatile(
        "mma.sync.aligned.m16n8k16.row.col.f32.f16.f16.f32 "
        "{%0,%1,%2,%3}, {%4,%5,%6,%7}, {%8,%9}, {%0,%1,%2,%3};\n"
        : "+f"(c[0]), "+f"(c[1]), "+f"(c[2]), "+f"(c[3])
        : "r"(a[0]), "r"(a[1]), "r"(a[2]), "r"(a[3]), "r"(b[0]), "r"(b[1]));
}

#define LDSM4(r0, r1, r2, r3, addr) \
    asm volatile("ldmatrix.sync.aligned.m8n8.x4.shared.b16 {%0,%1,%2,%3}, [%4];" \
                 : "=r"(r0), "=r"(r1), "=r"(r2), "=r"(r3) : "r"(addr))

__device__ __forceinline__ void cp16s(uint32_t daddr, const void* src, bool pred) {
    int sz = pred ? 16 : 0;
    asm volatile("cp.async.cg.shared.global [%0], [%1], 16, %2;\n"
                 :: "r"(daddr), "l"(src), "r"(sz));
}
__device__ __forceinline__ void cp_commit() { asm volatile("cp.async.commit_group;\n"); }
__device__ __forceinline__ void cp_wait1()  { asm volatile("cp.async.wait_group 1;\n"); }
__device__ __forceinline__ void cp_wait0()  { asm volatile("cp.async.wait_group 0;\n"); }

// ---------------- kernel 1: fused init + router --------------------------------
__global__ void init_router_kernel(const float* __restrict__ x,
                                   const float* __restrict__ rw,
                                   const float* __restrict__ rb,
                                   float* __restrict__ out) {
    int tid = threadIdx.x;
    if (blockIdx.x < 512) {
        int warp = tid >> 5, lane = tid & 31;
        int gw = blockIdx.x * 8 + warp;
        const float* xr = x + (size_t)gw * D_MODEL;
        float acc[NROUTED];
#pragma unroll
        for (int j = 0; j < NROUTED; j++) acc[j] = 0.f;
        for (int k = lane; k < D_MODEL; k += 32) {
            float xv = xr[k];
            const float* w = rw + k * NROUTED;
#pragma unroll
            for (int j = 0; j < NROUTED; j++) acc[j] += xv * w[j];
        }
#pragma unroll
        for (int j = 0; j < NROUTED; j++) {
#pragma unroll
            for (int o = 16; o > 0; o >>= 1)
                acc[j] += __shfl_xor_sync(0xffffffffu, acc[j], o);
        }
        if (lane == 0) {
            float lg[NROUTED];
#pragma unroll
            for (int j = 0; j < NROUTED; j++) lg[j] = acc[j] + rb[j];
            int i1 = 0;
#pragma unroll
            for (int j = 1; j < NROUTED; j++) if (lg[j] > lg[i1]) i1 = j;
            int i2 = (i1 == 0) ? 1 : 0;
#pragma unroll
            for (int j = 0; j < NROUTED; j++)
                if (j != i1 && lg[j] > lg[i2]) i2 = j;
            float m  = fmaxf(lg[i1], lg[i2]);
            float e1 = expf(lg[i1] - m), e2 = expf(lg[i2] - m);
            float s  = e1 + e2;
            d_topi[gw * 2] = i1;  d_topi[gw * 2 + 1] = i2;
            d_topw[gw * 2] = e1 / s;  d_topw[gw * 2 + 1] = e2 / s;
            atomicAdd(&d_cnt[i1], 1);
            atomicAdd(&d_cnt[i2], 1);
        }
    }
    int stride = gridDim.x * blockDim.x;
    int i = blockIdx.x * blockDim.x + tid;
    for (int j = i; j < T_TOK * D_MODEL; j += stride) {
        out[j] = 0.f;
        d_X[j] = __float2half_rn(x[j]);
    }
    for (int j = i; j < R_MAX; j += stride) {
        if (j < T_TOK) { d_tok[j] = j;  d_wrow[j] = 1.f; }
        else           { d_tok[j] = -1; d_wrow[j] = 0.f; }
    }
}

// ---------------- kernel 2: offsets + fill (single block) ----------------------
__global__ void offsfill_kernel() {
    int tid = threadIdx.x;
    if (tid == 0) {
        int base = T_TOK;
        for (int j = 0; j < NROUTED; j++) {
            d_off[j] = base;
            base += ((d_cnt[j] + BM - 1) / BM) * BM;
            d_cnt[j] = 0;   // reset for next replay
        }
        d_off[7] = base;
    }
    __syncthreads();
    for (int i = tid; i < T_TOK * 2; i += blockDim.x) {
        int t = i >> 1;
        int e = d_topi[i];
        float w = d_topw[i];
        int p = atomicAdd(&d_cnt2[e], 1);
        int r = d_off[e] + p;
        d_tok[r]  = t;
        d_wrow[r] = w;
    }
    __syncthreads();
    if (tid < NROUTED) d_cnt2[tid] = 0;
}

// ---------------- kernel 3: all weight transposes + fp16 convert ---------------
__global__ void tr_all_kernel(const float* __restrict__ wg,
                              const float* __restrict__ wu,
                              const float* __restrict__ wd) {
    __shared__ float t[32][33];
    int z = blockIdx.z;
    const float* s; __half* d; int R, C, e;
    if (z < 8)       { e = z;      s = wg; d = d_wgT; R = D_MODEL; C = DFF; }
    else if (z < 16) { e = z - 8;  s = wu; d = d_wuT; R = D_MODEL; C = DFF; }
    else             { e = z - 16; s = wd; d = d_wdT; R = DFF;     C = D_MODEL; }
    int c0 = blockIdx.x * 32, r0 = blockIdx.y * 32;
    if (c0 >= C || r0 >= R) return;
    s += (size_t)e * R * C;
    d += (size_t)e * R * C;
    int tx = threadIdx.x;
#pragma unroll
    for (int i = threadIdx.y; i < 32; i += 8)
        t[i][tx] = s[(size_t)(r0 + i) * C + c0 + tx];
    __syncthreads();
#pragma unroll
    for (int i = threadIdx.y; i < 32; i += 8)
        d[(size_t)(c0 + i) * R + r0 + tx] = __float2half_rn(t[tx][i]);
}

__device__ __forceinline__ int tile_expert(int row0) {
    if (row0 < T_TOK) return 0;
    int e = 0;
#pragma unroll
    for (int j = 0; j < NROUTED; j++)
        if (row0 >= d_off[j] && row0 < d_off[j + 1]) e = j + 1;
    return e;
}

// ---------------- gemm1: fp16 HMMA, fused gate+up, SiLU*u -> H -----------------
#define G1_STG  (3 * TILEB)
#define G1_SMEM (2 * G1_STG)        // 110592 B

__global__ __launch_bounds__(512, 1) void gemm1_kernel() {
    int row0 = blockIdx.x * BM;
    if (row0 >= d_off[7]) return;
    int e = tile_expert(row0);
    const __half* bg = d_wgT + (size_t)e * DFF * D_MODEL;
    const __half* bu = d_wuT + (size_t)e * DFF * D_MODEL;
    int n0 = blockIdx.y * 128;

    extern __shared__ char raw[];
    uint32_t base = smem_u32(raw);
    __shared__ int stok[128];

    int tid = threadIdx.x, warp = tid >> 5, lane = tid & 31;
    if (tid < 128) stok[tid] = d_tok[row0 + tid];
    __syncthreads();

    int wm = (warp >> 2) * 32, wn = (warp & 3) * 32;

    // cp.async chunk mapping: 1024 chunks per tile, 2 per thread per tile
    int ar[2], ac[2]; const __half* asrc[2]; const __half* gsrc[2]; const __half* usrc[2];
    bool apred[2];
#pragma unroll
    for (int i = 0; i < 2; i++) {
        int f = tid + i * 512;
        ar[i] = f >> 3; ac[i] = f & 7;             // row, 16B-chunk (8 fp16)
        int tok = stok[ar[i]];
        apred[i] = (tok >= 0);
        asrc[i] = d_X + (size_t)(apred[i] ? tok : 0) * D_MODEL + ac[i] * 8;
        gsrc[i] = bg + (size_t)(n0 + ar[i]) * D_MODEL + ac[i] * 8;
        usrc[i] = bu + (size_t)(n0 + ar[i]) * D_MODEL + ac[i] * 8;
    }

    // ldmatrix intra-tile byte offsets
    // A (m16xk16 x4): lanes 0-7 m0-7/k0-7, 8-15 m8-15/k0-7, 16-23 m0-7/k8-15, 24-31 m8-15/k8-15
    int arow = 8 * ((lane >> 3) & 1) + (lane & 7);
    int abyt = 16 * (lane >> 4);
    uint32_t aoff[2];
#pragma unroll
    for (int mi = 0; mi < 2; mi++)
        aoff[mi] = (uint32_t)((wm + mi * 16 + arow) * ROWB + abyt);
    // B ([N][K] rows; x4 = two n8 tiles x two k-halves)
    int brow = 8 * (lane >> 4) + (lane & 7);
    int bbyt = 16 * ((lane >> 3) & 1);
    uint32_t goff[2], uoff[2];
#pragma unroll
    for (int p = 0; p < 2; p++) {
        uint32_t o = (uint32_t)((wn + p * 16 + brow) * ROWB + bbyt);
        goff[p] = TILEB + o;
        uoff[p] = 2 * TILEB + o;
    }

    float accG[2][4][4], accU[2][4][4];
#pragma unroll
    for (int mi = 0; mi < 2; mi++)
#pragma unroll
        for (int ni = 0; ni < 4; ni++)
#pragma unroll
            for (int r = 0; r < 4; r++) { accG[mi][ni][r] = 0.f; accU[mi][ni][r] = 0.f; }

    // stage 0 prefetch
#pragma unroll
    for (int i = 0; i < 2; i++) {
        uint32_t d0 = base + ar[i] * ROWB + ac[i] * 16;
        cp16s(d0,             asrc[i], apred[i]);
        cp16s(d0 + TILEB,     gsrc[i], true);
        cp16s(d0 + 2 * TILEB, usrc[i], true);
    }
    cp_commit();

    const int KT = D_MODEL / BK;   // 16
    for (int kt = 0; kt < KT; kt++) {
        int cur = kt & 1;
        if (kt + 1 < KT) {
            int nk0 = (kt + 1) * BK;
            uint32_t S = base + ((kt + 1) & 1) * G1_STG;
#pragma unroll
            for (int i = 0; i < 2; i++) {
                uint32_t d0 = S + ar[i] * ROWB + ac[i] * 16;
                cp16s(d0,             asrc[i] + (apred[i] ? nk0 : 0), apred[i]);
                cp16s(d0 + TILEB,     gsrc[i] + nk0, true);
                cp16s(d0 + 2 * TILEB, usrc[i] + nk0, true);
            }
            cp_commit();
            cp_wait1();
        } else {
            cp_wait0();
        }
        __syncthreads();

        uint32_t S = base + cur * G1_STG;
#pragma unroll
        for (int ks = 0; ks < 4; ks++) {       // 4 x k16
            uint32_t a[2][4];
            LDSM4(a[0][0], a[0][1], a[0][2], a[0][3], S + aoff[0] + ks * 32);
            LDSM4(a[1][0], a[1][1], a[1][2], a[1][3], S + aoff[1] + ks * 32);
#pragma unroll
            for (int p = 0; p < 2; p++) {
                uint32_t g4[4], u4[4];
                LDSM4(g4[0], g4[1], g4[2], g4[3], S + goff[p] + ks * 32);
                LDSM4(u4[0], u4[1], u4[2], u4[3], S + uoff[p] + ks * 32);
                hmma(accG[0][2 * p],     a[0], g4 + 0);
                hmma(accG[1][2 * p],     a[1], g4 + 0);
                hmma(accG[0][2 * p + 1], a[0], g4 + 2);
                hmma(accG[1][2 * p + 1], a[1], g4 + 2);
                hmma(accU[0][2 * p],     a[0], u4 + 0);
                hmma(accU[1][2 * p],     a[1], u4 + 0);
                hmma(accU[0][2 * p + 1], a[0], u4 + 2);
                hmma(accU[1][2 * p + 1], a[1], u4 + 2);
            }
        }
        __syncthreads();
    }

    // epilogue: H = fp16(silu(g) * u)
#pragma unroll
    for (int mi = 0; mi < 2; mi++)
#pragma unroll
        for (int ni = 0; ni < 4; ni++)
#pragma unroll
            for (int rr = 0; rr < 4; rr++) {
                int rl = wm + mi * 16 + (lane >> 2) + ((rr >= 2) ? 8 : 0);
                if (stok[rl] < 0) continue;
                int col = n0 + wn + ni * 8 + 2 * (lane & 3) + (rr & 1);
                float g = accG[mi][ni][rr], u = accU[mi][ni][rr];
                float h = (g / (1.f + __expf(-g))) * u;
                d_H[(size_t)(row0 + rl) * DFF + col] = __float2half_rn(h);
            }
}

// ---------------- gemm2: fp16 HMMA down GEMM + weighted scatter-add ------------
#define G2_STG  (2 * TILEB)
#define G2_SMEM (2 * G2_STG)        // 73728 B

__global__ __launch_bounds__(512, 1) void gemm2_kernel(float* __restrict__ out) {
    int row0 = blockIdx.x * BM;
    if (row0 >= d_off[7]) return;
    int e = tile_expert(row0);
    const __half* bw = d_wdT + (size_t)e * DFF * D_MODEL;
    int n0 = blockIdx.y * 128;

    extern __shared__ char raw[];
    uint32_t base = smem_u32(raw);
    __shared__ int stok[128];
    __shared__ float swt[128];

    int tid = threadIdx.x, warp = tid >> 5, lane = tid & 31;
    if (tid < 128) { stok[tid] = d_tok[row0 + tid]; swt[tid] = d_wrow[row0 + tid]; }
    __syncthreads();

    int wm = (warp >> 2) * 32, wn = (warp & 3) * 32;

    int ar[2], ac[2]; bool apred[2]; const __half* asrc[2]; const __half* bsrc[2];
#pragma unroll
    for (int i = 0; i < 2; i++) {
        int f = tid + i * 512;
        ar[i] = f >> 3; ac[i] = f & 7;
        apred[i] = (stok[ar[i]] >= 0);
        asrc[i] = d_H + (size_t)(row0 + ar[i]) * DFF + ac[i] * 8;
        bsrc[i] = bw + (size_t)(n0 + ar[i]) * DFF + ac[i] * 8;
    }

    int arow = 8 * ((lane >> 3) & 1) + (lane & 7);
    int abyt = 16 * (lane >> 4);
    uint32_t aoff[2];
#pragma unroll
    for (int mi = 0; mi < 2; mi++)
        aoff[mi] = (uint32_t)((wm + mi * 16 + arow) * ROWB + abyt);
    int brow = 8 * (lane >> 4) + (lane & 7);
    int bbyt = 16 * ((lane >> 3) & 1);
    uint32_t boff[2];
#pragma unroll
    for (int p = 0; p < 2; p++)
        boff[p] = TILEB + (uint32_t)((wn + p * 16 + brow) * ROWB + bbyt);

    float acc[2][4][4];
#pragma unroll
    for (int mi = 0; mi < 2; mi++)
#pragma unroll
        for (int ni = 0; ni < 4; ni++)
#pragma unroll
            for (int r = 0; r < 4; r++) acc[mi][ni][r] = 0.f;

#pragma unroll
    for (int i = 0; i < 2; i++) {
        uint32_t d0 = base + ar[i] * ROWB + ac[i] * 16;
        cp16s(d0,         asrc[i], apred[i]);
        cp16s(d0 + TILEB, bsrc[i], true);
    }
    cp_commit();

    const int KT = DFF / BK;   // 32
    for (int kt = 0; kt < KT; kt++) {
        int cur = kt & 1;
        if (kt + 1 < KT) {
            int nk0 = (kt + 1) * BK;
            uint32_t S = base + ((kt + 1) & 1) * G2_STG;
#pragma unroll
            for (int i = 0; i < 2; i++) {
                uint32_t d0 = S + ar[i] * ROWB + ac[i] * 16;
                cp16s(d0,         asrc[i] + (apred[i] ? nk0 : 0), apred[i]);
                cp16s(d0 + TILEB, bsrc[i] + nk0, true);
            }
            cp_commit();
            cp_wait1();
        } else {
            cp_wait0();
        }
        __syncthreads();

        uint32_t S = base + cur * G2_STG;
#pragma unroll
        for (int ks = 0; ks < 4; ks++) {
            uint32_t a[2][4];
            LDSM4(a[0][0], a[0][1], a[0][2], a[0][3], S + aoff[0] + ks * 32);
            LDSM4(a[1][0], a[1][1], a[1][2], a[1][3], S + aoff[1] + ks * 32);
#pragma unroll
            for (int p = 0; p < 2; p++) {
                uint32_t b4[4];
                LDSM4(b4[0], b4[1], b4[2], b4[3], S + boff[p] + ks * 32);
                hmma(acc[0][2 * p],     a[0], b4 + 0);
                hmma(acc[1][2 * p],     a[1], b4 + 0);
                hmma(acc[0][2 * p + 1], a[0], b4 + 2);
                hmma(acc[1][2 * p + 1], a[1], b4 + 2);
            }
        }
        __syncthreads();
    }

#pragma unroll
    for (int mi = 0; mi < 2; mi++)
#pragma unroll
        for (int ni = 0; ni < 4; ni++)
#pragma unroll
            for (int rr = 0; rr < 4; rr++) {
                int rl = wm + mi * 16 + (lane >> 2) + ((rr >= 2) ? 8 : 0);
                int tok = stok[rl];
                if (tok < 0) continue;
                int col = n0 + wn + ni * 8 + 2 * (lane & 3) + (rr & 1);
                atomicAdd(out + (size_t)tok * D_MODEL + col, swt[rl] * acc[mi][ni][rr]);
            }
}

// ---------------- launch -------------------------------------------------------
extern "C" void kernel_launch(void* const* d_in, const int* in_sizes, int n_in,
                              void* d_out, int out_size) {
    const float* x  = (const float*)d_in[0];
    const float* rw = (const float*)d_in[1];
    const float* rb = (const float*)d_in[2];
    const float* wg = (const float*)d_in[3];
    const float* wu = (const float*)d_in[4];
    const float* wd = (const float*)d_in[5];
    float* out = (float*)d_out;
    (void)in_sizes; (void)n_in; (void)out_size;

    static bool attr_done = false;
    if (!attr_done) {
        cudaFuncSetAttribute(gemm1_kernel, cudaFuncAttributeMaxDynamicSharedMemorySize, G1_SMEM);
        cudaFuncSetAttribute(gemm2_kernel, cudaFuncAttributeMaxDynamicSharedMemorySize, G2_SMEM);
        attr_done = true;
    }

    // order keeps gemm1 as the 4th launch (ncu capture window)
    init_router_kernel<<<1024, 256>>>(x, rw, rb, out);
    offsfill_kernel<<<1, 1024>>>();
    tr_all_kernel<<<dim3(64, 64, 24), dim3(32, 8)>>>(wg, wu, wd);
    gemm1_kernel<<<dim3(NTILES_M, DFF / 128), 512, G1_SMEM>>>();
    gemm2_kernel<<<dim3(NTILES_M, D_MODEL / 128), 512, G2_SMEM>>>(out);
}

// round 7
// speedup vs baseline: 5.1372x; 1.0329x over previous
#include <cuda_runtime.h>
#include <cuda_fp16.h>
#include <cstdint>

// Problem constants
#define T_TOK   4096
#define D_MODEL 1024
#define DFF     2048
#define NROUTED 7
#define BM      128
#define BK      64
#define NTILES_M 104
#define R_MAX   (NTILES_M * BM)

// smem tile: 128 rows x 128B data (64 fp16), stride 144B -> conflict-free ldmatrix
#define ROWB   144
#define TILEB  (128 * ROWB)      // 18432 B
#define NSTAGE 3

// ---------------- scratch (static device globals; no allocations) -------------
__device__ __half d_H[(size_t)R_MAX * DFF];
__device__ __half d_X[(size_t)T_TOK * D_MODEL];
__device__ __half d_wgT[(size_t)8 * DFF * D_MODEL];   // [E][N=DFF][K=D]
__device__ __half d_wuT[(size_t)8 * DFF * D_MODEL];
__device__ __half d_wdT[(size_t)8 * D_MODEL * DFF];   // [E][N=D][K=DFF]
__device__ int    d_tok[R_MAX];
__device__ float  d_wrow[R_MAX];
__device__ int    d_off[8];
__device__ int    d_cnt[NROUTED];
__device__ int    d_cnt2[NROUTED];
__device__ int    d_topi[T_TOK * 2];
__device__ float  d_topw[T_TOK * 2];

// ---------------- helpers ----------------------------------------------------
__device__ __forceinline__ uint32_t smem_u32(const void* p) {
    uint32_t a;
    asm("{ .reg .u64 t; cvta.to.shared.u64 t, %1; cvt.u32.u64 %0, t; }"
        : "=r"(a) : "l"(p));
    return a;
}

__device__ __forceinline__ void hmma(float c[4], const uint32_t a[4], const uint32_t b[2]) {
    asm volatile(
        "mma.sync.aligned.m16n8k16.row.col.f32.f16.f16.f32 "
        "{%0,%1,%2,%3}, {%4,%5,%6,%7}, {%8,%9}, {%0,%1,%2,%3};\n"
        : "+f"(c[0]), "+f"(c[1]), "+f"(c[2]), "+f"(c[3])
        : "r"(a[0]), "r"(a[1]), "r"(a[2]), "r"(a[3]), "r"(b[0]), "r"(b[1]));
}

#define LDSM4(r0, r1, r2, r3, addr) \
    asm volatile("ldmatrix.sync.aligned.m8n8.x4.shared.b16 {%0,%1,%2,%3}, [%4];" \
                 : "=r"(r0), "=r"(r1), "=r"(r2), "=r"(r3) : "r"(addr))

__device__ __forceinline__ void cp16s(uint32_t daddr, const void* src, bool pred) {
    int sz = pred ? 16 : 0;
    asm volatile("cp.async.cg.shared.global [%0], [%1], 16, %2;\n"
                 :: "r"(daddr), "l"(src), "r"(sz));
}
__device__ __forceinline__ void cp_commit() { asm volatile("cp.async.commit_group;\n"); }
__device__ __forceinline__ void cp_wait2()  { asm volatile("cp.async.wait_group 2;\n"); }
__device__ __forceinline__ void cp_wait1()  { asm volatile("cp.async.wait_group 1;\n"); }
__device__ __forceinline__ void cp_wait0()  { asm volatile("cp.async.wait_group 0;\n"); }

__device__ __forceinline__ void mbar_init(uint32_t addr, uint32_t cnt) {
    asm volatile("mbarrier.init.shared.b64 [%0], %1;" :: "r"(addr), "r"(cnt) : "memory");
}
__device__ __forceinline__ void mbar_arrive(uint32_t addr) {
    asm volatile("mbarrier.arrive.shared.b64 _, [%0];" :: "r"(addr) : "memory");
}
__device__ __forceinline__ void mbar_wait(uint32_t addr, uint32_t parity) {
    asm volatile(
        "{\n\t.reg .pred P;\n\t"
        "W%=:\n\t"
        "mbarrier.try_wait.parity.acquire.cta.shared::cta.b64 P, [%0], %1, 0x989680;\n\t"
        "@!P bra W%=;\n\t}"
        :: "r"(addr), "r"(parity) : "memory");
}

// ---------------- kernel 1: fused init + router --------------------------------
__global__ void init_router_kernel(const float* __restrict__ x,
                                   const float* __restrict__ rw,
                                   const float* __restrict__ rb,
                                   float* __restrict__ out) {
    int tid = threadIdx.x;
    if (blockIdx.x < 512) {
        int warp = tid >> 5, lane = tid & 31;
        int gw = blockIdx.x * 8 + warp;
        const float* xr = x + (size_t)gw * D_MODEL;
        float acc[NROUTED];
#pragma unroll
        for (int j = 0; j < NROUTED; j++) acc[j] = 0.f;
        for (int k = lane; k < D_MODEL; k += 32) {
            float xv = xr[k];
            const float* w = rw + k * NROUTED;
#pragma unroll
            for (int j = 0; j < NROUTED; j++) acc[j] += xv * w[j];
        }
#pragma unroll
        for (int j = 0; j < NROUTED; j++) {
#pragma unroll
            for (int o = 16; o > 0; o >>= 1)
                acc[j] += __shfl_xor_sync(0xffffffffu, acc[j], o);
        }
        if (lane == 0) {
            float lg[NROUTED];
#pragma unroll
            for (int j = 0; j < NROUTED; j++) lg[j] = acc[j] + rb[j];
            int i1 = 0;
#pragma unroll
            for (int j = 1; j < NROUTED; j++) if (lg[j] > lg[i1]) i1 = j;
            int i2 = (i1 == 0) ? 1 : 0;
#pragma unroll
            for (int j = 0; j < NROUTED; j++)
                if (j != i1 && lg[j] > lg[i2]) i2 = j;
            float m  = fmaxf(lg[i1], lg[i2]);
            float e1 = expf(lg[i1] - m), e2 = expf(lg[i2] - m);
            float s  = e1 + e2;
            d_topi[gw * 2] = i1;  d_topi[gw * 2 + 1] = i2;
            d_topw[gw * 2] = e1 / s;  d_topw[gw * 2 + 1] = e2 / s;
            atomicAdd(&d_cnt[i1], 1);
            atomicAdd(&d_cnt[i2], 1);
        }
    }
    int stride = gridDim.x * blockDim.x;
    int i = blockIdx.x * blockDim.x + tid;
    for (int j = i; j < T_TOK * D_MODEL; j += stride) {
        out[j] = 0.f;
        d_X[j] = __float2half_rn(x[j]);
    }
    for (int j = i; j < R_MAX; j += stride) {
        if (j < T_TOK) { d_tok[j] = j;  d_wrow[j] = 1.f; }
        else           { d_tok[j] = -1; d_wrow[j] = 0.f; }
    }
}

// ---------------- kernel 2: offsets + fill (single block) ----------------------
__global__ void offsfill_kernel() {
    int tid = threadIdx.x;
    if (tid == 0) {
        int base = T_TOK;
        for (int j = 0; j < NROUTED; j++) {
            d_off[j] = base;
            base += ((d_cnt[j] + BM - 1) / BM) * BM;
            d_cnt[j] = 0;
        }
        d_off[7] = base;
    }
    __syncthreads();
    for (int i = tid; i < T_TOK * 2; i += blockDim.x) {
        int t = i >> 1;
        int e = d_topi[i];
        float w = d_topw[i];
        int p = atomicAdd(&d_cnt2[e], 1);
        int r = d_off[e] + p;
        d_tok[r]  = t;
        d_wrow[r] = w;
    }
    __syncthreads();
    if (tid < NROUTED) d_cnt2[tid] = 0;
}

// ---------------- kernel 3: weight transposes + fp16 convert -------------------
__global__ void tr_all_kernel(const float* __restrict__ wg,
                              const float* __restrict__ wu,
                              const float* __restrict__ wd) {
    __shared__ float t[32][33];
    int z = blockIdx.z;
    const float* s; __half* d; int R, C, e;
    if (z < 8)       { e = z;      s = wg; d = d_wgT; R = D_MODEL; C = DFF; }
    else if (z < 16) { e = z - 8;  s = wu; d = d_wuT; R = D_MODEL; C = DFF; }
    else             { e = z - 16; s = wd; d = d_wdT; R = DFF;     C = D_MODEL; }
    int c0 = blockIdx.x * 32, r0 = blockIdx.y * 32;
    if (c0 >= C || r0 >= R) return;
    s += (size_t)e * R * C;
    d += (size_t)e * R * C;
    int tx = threadIdx.x;
#pragma unroll
    for (int i = threadIdx.y; i < 32; i += 8)
        t[i][tx] = s[(size_t)(r0 + i) * C + c0 + tx];
    __syncthreads();
#pragma unroll
    for (int i = threadIdx.y; i < 32; i += 8)
        d[(size_t)(c0 + i) * R + r0 + tx] = __float2half_rn(t[tx][i]);
}

__device__ __forceinline__ int tile_expert(int row0) {
    if (row0 < T_TOK) return 0;
    int e = 0;
#pragma unroll
    for (int j = 0; j < NROUTED; j++)
        if (row0 >= d_off[j] && row0 < d_off[j + 1]) e = j + 1;
    return e;
}

// ---------------- gemm1: fp16 HMMA, 3-stage mbarrier pipeline ------------------
#define G1_STG  (3 * TILEB)
#define G1_SMEM (NSTAGE * G1_STG)        // 165888 B

__global__ __launch_bounds__(512, 1) void gemm1_kernel() {
    int row0 = blockIdx.x * BM;
    if (row0 >= d_off[7]) return;
    int e = tile_expert(row0);
    const __half* bg = d_wgT + (size_t)e * DFF * D_MODEL;
    const __half* bu = d_wuT + (size_t)e * DFF * D_MODEL;
    int n0 = blockIdx.y * 128;

    extern __shared__ char raw[];
    uint32_t base = smem_u32(raw);
    __shared__ int stok[128];
    __shared__ __align__(8) uint64_t s_mb[2 * NSTAGE];   // full[3], empty[3]

    int tid = threadIdx.x, warp = tid >> 5, lane = tid & 31;
    if (tid < 128) stok[tid] = d_tok[row0 + tid];
    uint32_t mbF = smem_u32(&s_mb[0]);
    uint32_t mbE = smem_u32(&s_mb[NSTAGE]);
    if (tid < NSTAGE)              mbar_init(mbF + tid * 8, 16);
    else if (tid < 2 * NSTAGE)     mbar_init(mbE + (tid - NSTAGE) * 8, 16);
    __syncthreads();

    int wm = (warp >> 2) * 32, wn = (warp & 3) * 32;

    // per-thread cp.async chunk mapping
    int ar[2], ac[2]; const __half* asrc[2]; const __half* gsrc[2]; const __half* usrc[2];
    bool apred[2];
#pragma unroll
    for (int i = 0; i < 2; i++) {
        int f = tid + i * 512;
        ar[i] = f >> 3; ac[i] = f & 7;
        int tok = stok[ar[i]];
        apred[i] = (tok >= 0);
        asrc[i] = d_X + (size_t)(apred[i] ? tok : 0) * D_MODEL + ac[i] * 8;
        gsrc[i] = bg + (size_t)(n0 + ar[i]) * D_MODEL + ac[i] * 8;
        usrc[i] = bu + (size_t)(n0 + ar[i]) * D_MODEL + ac[i] * 8;
    }

    auto issue = [&](int s, int ktile) {
        uint32_t S = base + s * G1_STG;
        int k0 = ktile * BK;
#pragma unroll
        for (int i = 0; i < 2; i++) {
            uint32_t d0 = S + ar[i] * ROWB + ac[i] * 16;
            cp16s(d0,             asrc[i] + (apred[i] ? k0 : 0), apred[i]);
            cp16s(d0 + TILEB,     gsrc[i] + k0, true);
            cp16s(d0 + 2 * TILEB, usrc[i] + k0, true);
        }
        cp_commit();
    };

    // ldmatrix intra-tile byte offsets
    int arow = 8 * ((lane >> 3) & 1) + (lane & 7);
    int abyt = 16 * (lane >> 4);
    uint32_t aoff[2];
#pragma unroll
    for (int mi = 0; mi < 2; mi++)
        aoff[mi] = (uint32_t)((wm + mi * 16 + arow) * ROWB + abyt);
    int brow = 8 * (lane >> 4) + (lane & 7);
    int bbyt = 16 * ((lane >> 3) & 1);
    uint32_t goff[2], uoff[2];
#pragma unroll
    for (int p = 0; p < 2; p++) {
        uint32_t o = (uint32_t)((wn + p * 16 + brow) * ROWB + bbyt);
        goff[p] = TILEB + o;
        uoff[p] = 2 * TILEB + o;
    }

    float accG[2][4][4], accU[2][4][4];
#pragma unroll
    for (int mi = 0; mi < 2; mi++)
#pragma unroll
        for (int ni = 0; ni < 4; ni++)
#pragma unroll
            for (int r = 0; r < 4; r++) { accG[mi][ni][r] = 0.f; accU[mi][ni][r] = 0.f; }

    const int KT = D_MODEL / BK;   // 16
    // prologue: fill all 3 stages
#pragma unroll
    for (int p = 0; p < NSTAGE; p++) issue(p, p);

    for (int kt = 0; kt < KT; kt++) {
        int s = kt % NSTAGE;
        uint32_t ph = (uint32_t)((kt / NSTAGE) & 1);
        uint32_t fB = mbF + s * 8, eB = mbE + s * 8;

        // certify my own stage-s copies (oldest group), then warp-arrive
        if (kt < KT - 2) cp_wait2(); else if (kt == KT - 2) cp_wait1(); else cp_wait0();
        __syncwarp();
        if (lane == 0) mbar_arrive(fB);
        mbar_wait(fB, ph);

        uint32_t S = base + s * G1_STG;
#pragma unroll
        for (int ks = 0; ks < 4; ks++) {
            uint32_t a[2][4];
            LDSM4(a[0][0], a[0][1], a[0][2], a[0][3], S + aoff[0] + ks * 32);
            LDSM4(a[1][0], a[1][1], a[1][2], a[1][3], S + aoff[1] + ks * 32);
#pragma unroll
            for (int p = 0; p < 2; p++) {
                uint32_t g4[4], u4[4];
                LDSM4(g4[0], g4[1], g4[2], g4[3], S + goff[p] + ks * 32);
                LDSM4(u4[0], u4[1], u4[2], u4[3], S + uoff[p] + ks * 32);
                hmma(accG[0][2 * p],     a[0], g4 + 0);
                hmma(accG[1][2 * p],     a[1], g4 + 0);
                hmma(accG[0][2 * p + 1], a[0], g4 + 2);
                hmma(accG[1][2 * p + 1], a[1], g4 + 2);
                hmma(accU[0][2 * p],     a[0], u4 + 0);
                hmma(accU[1][2 * p],     a[1], u4 + 0);
                hmma(accU[0][2 * p + 1], a[0], u4 + 2);
                hmma(accU[1][2 * p + 1], a[1], u4 + 2);
            }
        }
        __syncwarp();
        if (lane == 0) mbar_arrive(eB);

        if (kt + NSTAGE < KT) {
            mbar_wait(eB, ph);          // all warps done with stage s
            issue(s, kt + NSTAGE);
        }
    }

    // epilogue: H = fp16(silu(g) * u)
#pragma unroll
    for (int mi = 0; mi < 2; mi++)
#pragma unroll
        for (int ni = 0; ni < 4; ni++)
#pragma unroll
            for (int rr = 0; rr < 4; rr++) {
                int rl = wm + mi * 16 + (lane >> 2) + ((rr >= 2) ? 8 : 0);
                if (stok[rl] < 0) continue;
                int col = n0 + wn + ni * 8 + 2 * (lane & 3) + (rr & 1);
                float g = accG[mi][ni][rr], u = accU[mi][ni][rr];
                float h = (g / (1.f + __expf(-g))) * u;
                d_H[(size_t)(row0 + rl) * DFF + col] = __float2half_rn(h);
            }
}

// ---------------- gemm2: fp16 HMMA down GEMM + weighted scatter-add ------------
#define G2_STG  (2 * TILEB)
#define G2_SMEM (NSTAGE * G2_STG)        // 110592 B

__global__ __launch_bounds__(512, 1) void gemm2_kernel(float* __restrict__ out) {
    int row0 = blockIdx.x * BM;
    if (row0 >= d_off[7]) return;
    int e = tile_expert(row0);
    const __half* bw = d_wdT + (size_t)e * DFF * D_MODEL;
    int n0 = blockIdx.y * 128;

    extern __shared__ char raw[];
    uint32_t base = smem_u32(raw);
    __shared__ int stok[128];
    __shared__ float swt[128];
    __shared__ __align__(8) uint64_t s_mb[2 * NSTAGE];

    int tid = threadIdx.x, warp = tid >> 5, lane = tid & 31;
    if (tid < 128) { stok[tid] = d_tok[row0 + tid]; swt[tid] = d_wrow[row0 + tid]; }
    uint32_t mbF = smem_u32(&s_mb[0]);
    uint32_t mbE = smem_u32(&s_mb[NSTAGE]);
    if (tid < NSTAGE)              mbar_init(mbF + tid * 8, 16);
    else if (tid < 2 * NSTAGE)     mbar_init(mbE + (tid - NSTAGE) * 8, 16);
    __syncthreads();

    int wm = (warp >> 2) * 32, wn = (warp & 3) * 32;

    int ar[2], ac[2]; bool apred[2]; const __half* asrc[2]; const __half* bsrc[2];
#pragma unroll
    for (int i = 0; i < 2; i++) {
        int f = tid + i * 512;
        ar[i] = f >> 3; ac[i] = f & 7;
        apred[i] = (stok[ar[i]] >= 0);
        asrc[i] = d_H + (size_t)(row0 + ar[i]) * DFF + ac[i] * 8;
        bsrc[i] = bw + (size_t)(n0 + ar[i]) * DFF + ac[i] * 8;
    }

    auto issue = [&](int s, int ktile) {
        uint32_t S = base + s * G2_STG;
        int k0 = ktile * BK;
#pragma unroll
        for (int i = 0; i < 2; i++) {
            uint32_t d0 = S + ar[i] * ROWB + ac[i] * 16;
            cp16s(d0,         asrc[i] + (apred[i] ? k0 : 0), apred[i]);
            cp16s(d0 + TILEB, bsrc[i] + k0, true);
        }
        cp_commit();
    };

    int arow = 8 * ((lane >> 3) & 1) + (lane & 7);
    int abyt = 16 * (lane >> 4);
    uint32_t aoff[2];
#pragma unroll
    for (int mi = 0; mi < 2; mi++)
        aoff[mi] = (uint32_t)((wm + mi * 16 + arow) * ROWB + abyt);
    int brow = 8 * (lane >> 4) + (lane & 7);
    int bbyt = 16 * ((lane >> 3) & 1);
    uint32_t boff[2];
#pragma unroll
    for (int p = 0; p < 2; p++)
        boff[p] = TILEB + (uint32_t)((wn + p * 16 + brow) * ROWB + bbyt);

    float acc[2][4][4];
#pragma unroll
    for (int mi = 0; mi < 2; mi++)
#pragma unroll
        for (int ni = 0; ni < 4; ni++)
#pragma unroll
            for (int r = 0; r < 4; r++) acc[mi][ni][r] = 0.f;

    const int KT = DFF / BK;   // 32
#pragma unroll
    for (int p = 0; p < NSTAGE; p++) issue(p, p);

    for (int kt = 0; kt < KT; kt++) {
        int s = kt % NSTAGE;
        uint32_t ph = (uint32_t)((kt / NSTAGE) & 1);
        uint32_t fB = mbF + s * 8, eB = mbE + s * 8;

        if (kt < KT - 2) cp_wait2(); else if (kt == KT - 2) cp_wait1(); else cp_wait0();
        __syncwarp();
        if (lane == 0) mbar_arrive(fB);
        mbar_wait(fB, ph);

        uint32_t S = base + s * G2_STG;
#pragma unroll
        for (int ks = 0; ks < 4; ks++) {
            uint32_t a[2][4];
            LDSM4(a[0][0], a[0][1], a[0][2], a[0][3], S + aoff[0] + ks * 32);
            LDSM4(a[1][0], a[1][1], a[1][2], a[1][3], S + aoff[1] + ks * 32);
#pragma unroll
            for (int p = 0; p < 2; p++) {
                uint32_t b4[4];
                LDSM4(b4[0], b4[1], b4[2], b4[3], S + boff[p] + ks * 32);
                hmma(acc[0][2 * p],     a[0], b4 + 0);
                hmma(acc[1][2 * p],     a[1], b4 + 0);
                hmma(acc[0][2 * p + 1], a[0], b4 + 2);
                hmma(acc[1][2 * p + 1], a[1], b4 + 2);
            }
        }
        __syncwarp();
        if (lane == 0) mbar_arrive(eB);

        if (kt + NSTAGE < KT) {
            mbar_wait(eB, ph);
            issue(s, kt + NSTAGE);
        }
    }

#pragma unroll
    for (int mi = 0; mi < 2; mi++)
#pragma unroll
        for (int ni = 0; ni < 4; ni++)
#pragma unroll
            for (int rr = 0; rr < 4; rr++) {
                int rl = wm + mi * 16 + (lane >> 2) + ((rr >= 2) ? 8 : 0);
                int tok = stok[rl];
                if (tok < 0) continue;
                int col = n0 + wn + ni * 8 + 2 * (lane & 3) + (rr & 1);
                atomicAdd(out + (size_t)tok * D_MODEL + col, swt[rl] * acc[mi][ni][rr]);
            }
}

// ---------------- launch -------------------------------------------------------
extern "C" void kernel_launch(void* const* d_in, const int* in_sizes, int n_in,
                              void* d_out, int out_size) {
    const float* x  = (const float*)d_in[0];
    const float* rw = (const float*)d_in[1];
    const float* rb = (const float*)d_in[2];
    const float* wg = (const float*)d_in[3];
    const float* wu = (const float*)d_in[4];
    const float* wd = (const float*)d_in[5];
    float* out = (float*)d_out;
    (void)in_sizes; (void)n_in; (void)out_size;

    static bool attr_done = false;
    if (!attr_done) {
        cudaFuncSetAttribute(gemm1_kernel, cudaFuncAttributeMaxDynamicSharedMemorySize, G1_SMEM);
        cudaFuncSetAttribute(gemm2_kernel, cudaFuncAttributeMaxDynamicSharedMemorySize, G2_SMEM);
        attr_done = true;
    }

    // order keeps gemm1 as the 4th launch (ncu capture window)
    init_router_kernel<<<1024, 256>>>(x, rw, rb, out);
    offsfill_kernel<<<1, 1024>>>();
    tr_all_kernel<<<dim3(64, 64, 24), dim3(32, 8)>>>(wg, wu, wd);
    gemm1_kernel<<<dim3(NTILES_M, DFF / 128), 512, G1_SMEM>>>();
    gemm2_kernel<<<dim3(NTILES_M, D_MODEL / 128), 512, G2_SMEM>>>(out);
}

// round 8
// speedup vs baseline: 5.4950x; 1.0696x over previous
#include <cuda_runtime.h>
#include <cuda_fp16.h>
#include <cstdint>

// Problem constants
#define T_TOK   4096
#define D_MODEL 1024
#define DFF     2048
#define NROUTED 7
#define BM      128
#define BK      64
#define NTILES_M 104
#define R_MAX   (NTILES_M * BM)

// smem tile: 128 rows x 128B data (64 fp16), stride 144B -> conflict-free ldmatrix
#define ROWB   144
#define TILEB  (128 * ROWB)      // 18432 B
#define NSTAGE 3

// prep grid split
#define NROUTER_BLKS 512
#define NTR_BLKS     (24 * 2048)     // 24 matrices x 2048 32x32 tiles
#define PREP_BLKS    (NROUTER_BLKS + NTR_BLKS)

// ---------------- scratch (static device globals; no allocations) -------------
__device__ __half d_H[(size_t)R_MAX * DFF];
__device__ __half d_X[(size_t)T_TOK * D_MODEL];
__device__ __half d_wgT[(size_t)8 * DFF * D_MODEL];   // [E][N=DFF][K=D]
__device__ __half d_wuT[(size_t)8 * DFF * D_MODEL];
__device__ __half d_wdT[(size_t)8 * D_MODEL * DFF];   // [E][N=D][K=DFF]
__device__ int    d_tok[R_MAX];
__device__ float  d_wrow[R_MAX];
__device__ int    d_off[8];
__device__ int    d_cnt[NROUTED];
__device__ int    d_cnt2[NROUTED];
__device__ int    d_topi[T_TOK * 2];
__device__ float  d_topw[T_TOK * 2];

// ---------------- helpers ----------------------------------------------------
__device__ __forceinline__ uint32_t smem_u32(const void* p) {
    uint32_t a;
    asm("{ .reg .u64 t; cvta.to.shared.u64 t, %1; cvt.u32.u64 %0, t; }"
        : "=r"(a) : "l"(p));
    return a;
}

__device__ __forceinline__ void hmma(float c[4], const uint32_t a[4], const uint32_t b[2]) {
    asm volatile(
        "mma.sync.aligned.m16n8k16.row.col.f32.f16.f16.f32 "
        "{%0,%1,%2,%3}, {%4,%5,%6,%7}, {%8,%9}, {%0,%1,%2,%3};\n"
        : "+f"(c[0]), "+f"(c[1]), "+f"(c[2]), "+f"(c[3])
        : "r"(a[0]), "r"(a[1]), "r"(a[2]), "r"(a[3]), "r"(b[0]), "r"(b[1]));
}

#define LDSM4(r0, r1, r2, r3, addr) \
    asm volatile("ldmatrix.sync.aligned.m8n8.x4.shared.b16 {%0,%1,%2,%3}, [%4];" \
                 : "=r"(r0), "=r"(r1), "=r"(r2), "=r"(r3) : "r"(addr))

__device__ __forceinline__ void cp16s(uint32_t daddr, const void* src, bool pred) {
    int sz = pred ? 16 : 0;
    asm volatile("cp.async.cg.shared.global [%0], [%1], 16, %2;\n"
                 :: "r"(daddr), "l"(src), "r"(sz));
}
__device__ __forceinline__ void cp_commit() { asm volatile("cp.async.commit_group;\n"); }
__device__ __forceinline__ void cp_wait2()  { asm volatile("cp.async.wait_group 2;\n"); }
__device__ __forceinline__ void cp_wait1()  { asm volatile("cp.async.wait_group 1;\n"); }
__device__ __forceinline__ void cp_wait0()  { asm volatile("cp.async.wait_group 0;\n"); }

__device__ __forceinline__ void mbar_init(uint32_t addr, uint32_t cnt) {
    asm volatile("mbarrier.init.shared.b64 [%0], %1;" :: "r"(addr), "r"(cnt) : "memory");
}
__device__ __forceinline__ void mbar_arrive(uint32_t addr) {
    asm volatile("mbarrier.arrive.shared.b64 _, [%0];" :: "r"(addr) : "memory");
}
__device__ __forceinline__ void mbar_wait(uint32_t addr, uint32_t parity) {
    asm volatile(
        "{\n\t.reg .pred P;\n\t"
        "W%=:\n\t"
        "mbarrier.try_wait.parity.acquire.cta.shared::cta.b64 P, [%0], %1, 0x989680;\n\t"
        "@!P bra W%=;\n\t}"
        :: "r"(addr), "r"(parity) : "memory");
}

// ---------------- kernel 1: fused prep (init + router + transpose/convert) -----
__global__ void prep_kernel(const float* __restrict__ x,
                            const float* __restrict__ rw,
                            const float* __restrict__ rb,
                            const float* __restrict__ wg,
                            const float* __restrict__ wu,
                            const float* __restrict__ wd,
                            float* __restrict__ out) {
    int tid = threadIdx.x;
    int b = blockIdx.x;

    if (b < NROUTER_BLKS) {
        // ---- router: 8 warps = 8 tokens per block ----
        int warp = tid >> 5, lane = tid & 31;
        int gw = b * 8 + warp;
        const float* xr = x + (size_t)gw * D_MODEL;
        float acc[NROUTED];
#pragma unroll
        for (int j = 0; j < NROUTED; j++) acc[j] = 0.f;
        for (int k = lane; k < D_MODEL; k += 32) {
            float xv = xr[k];
            const float* w = rw + k * NROUTED;
#pragma unroll
            for (int j = 0; j < NROUTED; j++) acc[j] += xv * w[j];
        }
#pragma unroll
        for (int j = 0; j < NROUTED; j++) {
#pragma unroll
            for (int o = 16; o > 0; o >>= 1)
                acc[j] += __shfl_xor_sync(0xffffffffu, acc[j], o);
        }
        if (lane == 0) {
            float lg[NROUTED];
#pragma unroll
            for (int j = 0; j < NROUTED; j++) lg[j] = acc[j] + rb[j];
            int i1 = 0;
#pragma unroll
            for (int j = 1; j < NROUTED; j++) if (lg[j] > lg[i1]) i1 = j;
            int i2 = (i1 == 0) ? 1 : 0;
#pragma unroll
            for (int j = 0; j < NROUTED; j++)
                if (j != i1 && lg[j] > lg[i2]) i2 = j;
            float m  = fmaxf(lg[i1], lg[i2]);
            float e1 = expf(lg[i1] - m), e2 = expf(lg[i2] - m);
            float s  = e1 + e2;
            d_topi[gw * 2] = i1;  d_topi[gw * 2 + 1] = i2;
            d_topw[gw * 2] = e1 / s;  d_topw[gw * 2 + 1] = e2 / s;
            atomicAdd(&d_cnt[i1], 1);
            atomicAdd(&d_cnt[i2], 1);
        }
    } else {
        // ---- weight transpose + fp16 convert: one 32x32 tile per block ----
        __shared__ float t[32][33];
        int bt = b - NROUTER_BLKS;
        int z = bt >> 11;              // / 2048
        int ti = bt & 2047;
        const float* s; __half* d; int R, C, e, cx, ry;
        if (z < 16) {
            e = z & 7; s = (z < 8) ? wg : wu; d = (z < 8) ? d_wgT : d_wuT;
            R = D_MODEL; C = DFF;
            cx = ti & 63; ry = ti >> 6;            // 64 x 32
        } else {
            e = z - 16; s = wd; d = d_wdT;
            R = DFF; C = D_MODEL;
            cx = ti & 31; ry = ti >> 5;            // 32 x 64
        }
        int c0 = cx * 32, r0 = ry * 32;
        s += (size_t)e * R * C;
        d += (size_t)e * R * C;
        int tx = tid & 31, ty = tid >> 5;
#pragma unroll
        for (int i = ty; i < 32; i += 8)
            t[i][tx] = s[(size_t)(r0 + i) * C + c0 + tx];
        __syncthreads();
#pragma unroll
        for (int i = ty; i < 32; i += 8)
            d[(size_t)(c0 + i) * R + r0 + tx] = __float2half_rn(t[tx][i]);
    }

    // ---- init duty: all blocks, grid-stride ----
    int stride = gridDim.x * blockDim.x;
    int i = b * blockDim.x + tid;
    for (int j = i; j < T_TOK * D_MODEL; j += stride) {
        out[j] = 0.f;
        d_X[j] = __float2half_rn(x[j]);
    }
    for (int j = i; j < R_MAX; j += stride) {
        if (j < T_TOK) { d_tok[j] = j;  d_wrow[j] = 1.f; }
        else           { d_tok[j] = -1; d_wrow[j] = 0.f; }
    }
}

// ---------------- kernel 2: offsets + fill (single block) ----------------------
__global__ void offsfill_kernel() {
    int tid = threadIdx.x;
    if (tid == 0) {
        int base = T_TOK;
        for (int j = 0; j < NROUTED; j++) {
            d_off[j] = base;
            base += ((d_cnt[j] + BM - 1) / BM) * BM;
            d_cnt[j] = 0;
        }
        d_off[7] = base;
    }
    __syncthreads();
    for (int i = tid; i < T_TOK * 2; i += blockDim.x) {
        int t = i >> 1;
        int e = d_topi[i];
        float w = d_topw[i];
        int p = atomicAdd(&d_cnt2[e], 1);
        int r = d_off[e] + p;
        d_tok[r]  = t;
        d_wrow[r] = w;
    }
    __syncthreads();
    if (tid < NROUTED) d_cnt2[tid] = 0;
}

__device__ __forceinline__ int tile_expert(int row0) {
    if (row0 < T_TOK) return 0;
    int e = 0;
#pragma unroll
    for (int j = 0; j < NROUTED; j++)
        if (row0 >= d_off[j] && row0 < d_off[j + 1]) e = j + 1;
    return e;
}

// ---------------- gemm1: 256 thr, 8 warps (2m x 4n), warp tile 64x32 -----------
#define G1_STG  (3 * TILEB)
#define G1_SMEM (NSTAGE * G1_STG)        // 165888 B

__global__ __launch_bounds__(256, 1) void gemm1_kernel() {
    int row0 = blockIdx.x * BM;
    if (row0 >= d_off[7]) return;
    int e = tile_expert(row0);
    const __half* bg = d_wgT + (size_t)e * DFF * D_MODEL;
    const __half* bu = d_wuT + (size_t)e * DFF * D_MODEL;
    int n0 = blockIdx.y * 128;

    extern __shared__ char raw[];
    uint32_t base = smem_u32(raw);
    __shared__ int stok[128];
    __shared__ __align__(8) uint64_t s_mb[2 * NSTAGE];

    int tid = threadIdx.x, warp = tid >> 5, lane = tid & 31;
    if (tid < 128) stok[tid] = d_tok[row0 + tid];
    uint32_t mbF = smem_u32(&s_mb[0]);
    uint32_t mbE = smem_u32(&s_mb[NSTAGE]);
    if (tid < NSTAGE)              mbar_init(mbF + tid * 8, 8);
    else if (tid < 2 * NSTAGE)     mbar_init(mbE + (tid - NSTAGE) * 8, 8);
    __syncthreads();

    int wm = (warp >> 2) * 64, wn = (warp & 3) * 32;

    // per-thread cp.async chunk mapping: 1024 chunks, 4 per thread
    int ar[4], ac[4]; const __half* asrc[4]; const __half* gsrc[4]; const __half* usrc[4];
    bool apred[4];
#pragma unroll
    for (int i = 0; i < 4; i++) {
        int f = tid + i * 256;
        ar[i] = f >> 3; ac[i] = f & 7;
        int tok = stok[ar[i]];
        apred[i] = (tok >= 0);
        asrc[i] = d_X + (size_t)(apred[i] ? tok : 0) * D_MODEL + ac[i] * 8;
        gsrc[i] = bg + (size_t)(n0 + ar[i]) * D_MODEL + ac[i] * 8;
        usrc[i] = bu + (size_t)(n0 + ar[i]) * D_MODEL + ac[i] * 8;
    }

    auto issue = [&](int s, int ktile) {
        uint32_t S = base + s * G1_STG;
        int k0 = ktile * BK;
#pragma unroll
        for (int i = 0; i < 4; i++) {
            uint32_t d0 = S + ar[i] * ROWB + ac[i] * 16;
            cp16s(d0,             asrc[i] + (apred[i] ? k0 : 0), apred[i]);
            cp16s(d0 + TILEB,     gsrc[i] + k0, true);
            cp16s(d0 + 2 * TILEB, usrc[i] + k0, true);
        }
        cp_commit();
    };

    // ldmatrix intra-tile byte offsets
    int arow = 8 * ((lane >> 3) & 1) + (lane & 7);
    int abyt = 16 * (lane >> 4);
    uint32_t aoff[4];
#pragma unroll
    for (int mi = 0; mi < 4; mi++)
        aoff[mi] = (uint32_t)((wm + mi * 16 + arow) * ROWB + abyt);
    int brow = 8 * (lane >> 4) + (lane & 7);
    int bbyt = 16 * ((lane >> 3) & 1);
    uint32_t goff[2], uoff[2];
#pragma unroll
    for (int p = 0; p < 2; p++) {
        uint32_t o = (uint32_t)((wn + p * 16 + brow) * ROWB + bbyt);
        goff[p] = TILEB + o;
        uoff[p] = 2 * TILEB + o;
    }

    float accG[4][4][4], accU[4][4][4];
#pragma unroll
    for (int mi = 0; mi < 4; mi++)
#pragma unroll
        for (int ni = 0; ni < 4; ni++)
#pragma unroll
            for (int r = 0; r < 4; r++) { accG[mi][ni][r] = 0.f; accU[mi][ni][r] = 0.f; }

    const int KT = D_MODEL / BK;   // 16
#pragma unroll
    for (int p = 0; p < NSTAGE; p++) issue(p, p);

    for (int kt = 0; kt < KT; kt++) {
        int s = kt % NSTAGE;
        uint32_t ph = (uint32_t)((kt / NSTAGE) & 1);
        uint32_t fB = mbF + s * 8, eB = mbE + s * 8;

        if (kt < KT - 2) cp_wait2(); else if (kt == KT - 2) cp_wait1(); else cp_wait0();
        __syncwarp();
        if (lane == 0) mbar_arrive(fB);
        mbar_wait(fB, ph);

        uint32_t S = base + s * G1_STG;
#pragma unroll
        for (int ks = 0; ks < 4; ks++) {
            uint32_t a[4][4];
#pragma unroll
            for (int mi = 0; mi < 4; mi++)
                LDSM4(a[mi][0], a[mi][1], a[mi][2], a[mi][3], S + aoff[mi] + ks * 32);
#pragma unroll
            for (int p = 0; p < 2; p++) {
                uint32_t g4[4], u4[4];
                LDSM4(g4[0], g4[1], g4[2], g4[3], S + goff[p] + ks * 32);
                LDSM4(u4[0], u4[1], u4[2], u4[3], S + uoff[p] + ks * 32);
#pragma unroll
                for (int mi = 0; mi < 4; mi++) {
                    hmma(accG[mi][2 * p],     a[mi], g4 + 0);
                    hmma(accG[mi][2 * p + 1], a[mi], g4 + 2);
                    hmma(accU[mi][2 * p],     a[mi], u4 + 0);
                    hmma(accU[mi][2 * p + 1], a[mi], u4 + 2);
                }
            }
        }
        __syncwarp();
        if (lane == 0) mbar_arrive(eB);

        if (kt + NSTAGE < KT) {
            mbar_wait(eB, ph);
            issue(s, kt + NSTAGE);
        }
    }

    // epilogue: H = fp16(silu(g) * u)
#pragma unroll
    for (int mi = 0; mi < 4; mi++)
#pragma unroll
        for (int ni = 0; ni < 4; ni++)
#pragma unroll
            for (int rr = 0; rr < 4; rr++) {
                int rl = wm + mi * 16 + (lane >> 2) + ((rr >= 2) ? 8 : 0);
                if (stok[rl] < 0) continue;
                int col = n0 + wn + ni * 8 + 2 * (lane & 3) + (rr & 1);
                float g = accG[mi][ni][rr], u = accU[mi][ni][rr];
                float h = (g / (1.f + __expf(-g))) * u;
                d_H[(size_t)(row0 + rl) * DFF + col] = __float2half_rn(h);
            }
}

// ---------------- gemm2: 256 thr, warp tile 64x32, down GEMM + scatter ---------
#define G2_STG  (2 * TILEB)
#define G2_SMEM (NSTAGE * G2_STG)        // 110592 B

__global__ __launch_bounds__(256, 1) void gemm2_kernel(float* __restrict__ out) {
    int row0 = blockIdx.x * BM;
    if (row0 >= d_off[7]) return;
    int e = tile_expert(row0);
    const __half* bw = d_wdT + (size_t)e * DFF * D_MODEL;
    int n0 = blockIdx.y * 128;

    extern __shared__ char raw[];
    uint32_t base = smem_u32(raw);
    __shared__ int stok[128];
    __shared__ float swt[128];
    __shared__ __align__(8) uint64_t s_mb[2 * NSTAGE];

    int tid = threadIdx.x, warp = tid >> 5, lane = tid & 31;
    if (tid < 128) { stok[tid] = d_tok[row0 + tid]; swt[tid] = d_wrow[row0 + tid]; }
    uint32_t mbF = smem_u32(&s_mb[0]);
    uint32_t mbE = smem_u32(&s_mb[NSTAGE]);
    if (tid < NSTAGE)              mbar_init(mbF + tid * 8, 8);
    else if (tid < 2 * NSTAGE)     mbar_init(mbE + (tid - NSTAGE) * 8, 8);
    __syncthreads();

    int wm = (warp >> 2) * 64, wn = (warp & 3) * 32;

    int ar[4], ac[4]; bool apred[4]; const __half* asrc[4]; const __half* bsrc[4];
#pragma unroll
    for (int i = 0; i < 4; i++) {
        int f = tid + i * 256;
        ar[i] = f >> 3; ac[i] = f & 7;
        apred[i] = (stok[ar[i]] >= 0);
        asrc[i] = d_H + (size_t)(row0 + ar[i]) * DFF + ac[i] * 8;
        bsrc[i] = bw + (size_t)(n0 + ar[i]) * DFF + ac[i] * 8;
    }

    auto issue = [&](int s, int ktile) {
        uint32_t S = base + s * G2_STG;
        int k0 = ktile * BK;
#pragma unroll
        for (int i = 0; i < 4; i++) {
            uint32_t d0 = S + ar[i] * ROWB + ac[i] * 16;
            cp16s(d0,         asrc[i] + (apred[i] ? k0 : 0), apred[i]);
            cp16s(d0 + TILEB, bsrc[i] + k0, true);
        }
        cp_commit();
    };

    int arow = 8 * ((lane >> 3) & 1) + (lane & 7);
    int abyt = 16 * (lane >> 4);
    uint32_t aoff[4];
#pragma unroll
    for (int mi = 0; mi < 4; mi++)
        aoff[mi] = (uint32_t)((wm + mi * 16 + arow) * ROWB + abyt);
    int brow = 8 * (lane >> 4) + (lane & 7);
    int bbyt = 16 * ((lane >> 3) & 1);
    uint32_t boff[2];
#pragma unroll
    for (int p = 0; p < 2; p++)
        boff[p] = TILEB + (uint32_t)((wn + p * 16 + brow) * ROWB + bbyt);

    float acc[4][4][4];
#pragma unroll
    for (int mi = 0; mi < 4; mi++)
#pragma unroll
        for (int ni = 0; ni < 4; ni++)
#pragma unroll
            for (int r = 0; r < 4; r++) acc[mi][ni][r] = 0.f;

    const int KT = DFF / BK;   // 32
#pragma unroll
    for (int p = 0; p < NSTAGE; p++) issue(p, p);

    for (int kt = 0; kt < KT; kt++) {
        int s = kt % NSTAGE;
        uint32_t ph = (uint32_t)((kt / NSTAGE) & 1);
        uint32_t fB = mbF + s * 8, eB = mbE + s * 8;

        if (kt < KT - 2) cp_wait2(); else if (kt == KT - 2) cp_wait1(); else cp_wait0();
        __syncwarp();
        if (lane == 0) mbar_arrive(fB);
        mbar_wait(fB, ph);

        uint32_t S = base + s * G2_STG;
#pragma unroll
        for (int ks = 0; ks < 4; ks++) {
            uint32_t a[4][4];
#pragma unroll
            for (int mi = 0; mi < 4; mi++)
                LDSM4(a[mi][0], a[mi][1], a[mi][2], a[mi][3], S + aoff[mi] + ks * 32);
#pragma unroll
            for (int p = 0; p < 2; p++) {
                uint32_t b4[4];
                LDSM4(b4[0], b4[1], b4[2], b4[3], S + boff[p] + ks * 32);
#pragma unroll
                for (int mi = 0; mi < 4; mi++) {
                    hmma(acc[mi][2 * p],     a[mi], b4 + 0);
                    hmma(acc[mi][2 * p + 1], a[mi], b4 + 2);
                }
            }
        }
        __syncwarp();
        if (lane == 0) mbar_arrive(eB);

        if (kt + NSTAGE < KT) {
            mbar_wait(eB, ph);
            issue(s, kt + NSTAGE);
        }
    }

#pragma unroll
    for (int mi = 0; mi < 4; mi++)
#pragma unroll
        for (int ni = 0; ni < 4; ni++)
#pragma unroll
            for (int rr = 0; rr < 4; rr++) {
                int rl = wm + mi * 16 + (lane >> 2) + ((rr >= 2) ? 8 : 0);
                int tok = stok[rl];
                if (tok < 0) continue;
                int col = n0 + wn + ni * 8 + 2 * (lane & 3) + (rr & 1);
                atomicAdd(out + (size_t)tok * D_MODEL + col, swt[rl] * acc[mi][ni][rr]);
            }
}

// ---------------- launch -------------------------------------------------------
extern "C" void kernel_launch(void* const* d_in, const int* in_sizes, int n_in,
                              void* d_out, int out_size) {
    const float* x  = (const float*)d_in[0];
    const float* rw = (const float*)d_in[1];
    const float* rb = (const float*)d_in[2];
    const float* wg = (const float*)d_in[3];
    const float* wu = (const float*)d_in[4];
    const float* wd = (const float*)d_in[5];
    float* out = (float*)d_out;
    (void)in_sizes; (void)n_in; (void)out_size;

    static bool attr_done = false;
    if (!attr_done) {
        cudaFuncSetAttribute(gemm1_kernel, cudaFuncAttributeMaxDynamicSharedMemorySize, G1_SMEM);
        cudaFuncSetAttribute(gemm2_kernel, cudaFuncAttributeMaxDynamicSharedMemorySize, G2_SMEM);
        attr_done = true;
    }

    prep_kernel<<<PREP_BLKS, 256>>>(x, rw, rb, wg, wu, wd, out);
    offsfill_kernel<<<1, 1024>>>();
    gemm1_kernel<<<dim3(NTILES_M, DFF / 128), 256, G1_SMEM>>>();
    gemm2_kernel<<<dim3(NTILES_M, D_MODEL / 128), 256, G2_SMEM>>>(out);
}

// round 9
// speedup vs baseline: 5.7527x; 1.0469x over previous
#include <cuda_runtime.h>
#include <cuda_fp16.h>
#include <cstdint>

// Problem constants
#define T_TOK   4096
#define D_MODEL 1024
#define DFF     2048
#define NROUTED 7
#define BM      128
#define BK      64
#define NTILES_M 104
#define R_MAX   (NTILES_M * BM)

// smem tile: 128 rows x 128B data (64 fp16), stride 144B -> conflict-free ldmatrix
#define ROWB   144
#define TILEB  (128 * ROWB)      // 18432 B
#define NSTAGE 3

// ---------------- scratch (static device globals; no allocations) -------------
__device__ __half d_H[(size_t)R_MAX * DFF];
__device__ __half d_X[(size_t)T_TOK * D_MODEL];
__device__ __half d_wgT[(size_t)8 * DFF * D_MODEL];   // [E][N=DFF][K=D]
__device__ __half d_wuT[(size_t)8 * DFF * D_MODEL];
__device__ __half d_wdT[(size_t)8 * D_MODEL * DFF];   // [E][N=D][K=DFF]
__device__ int    d_tok[R_MAX];
__device__ float  d_wrow[R_MAX];
__device__ int    d_off[8];
__device__ int    d_cnt[NROUTED];
__device__ int    d_cnt2[NROUTED];
__device__ int    d_topi[T_TOK * 2];
__device__ float  d_topw[T_TOK * 2];

// ---------------- helpers ----------------------------------------------------
__device__ __forceinline__ uint32_t smem_u32(const void* p) {
    uint32_t a;
    asm("{ .reg .u64 t; cvta.to.shared.u64 t, %1; cvt.u32.u64 %0, t; }"
        : "=r"(a) : "l"(p));
    return a;
}

__device__ __forceinline__ void hmma(float c[4], const uint32_t a[4], const uint32_t b[2]) {
    asm volatile(
        "mma.sync.aligned.m16n8k16.row.col.f32.f16.f16.f32 "
        "{%0,%1,%2,%3}, {%4,%5,%6,%7}, {%8,%9}, {%0,%1,%2,%3};\n"
        : "+f"(c[0]), "+f"(c[1]), "+f"(c[2]), "+f"(c[3])
        : "r"(a[0]), "r"(a[1]), "r"(a[2]), "r"(a[3]), "r"(b[0]), "r"(b[1]));
}

#define LDSM4(r0, r1, r2, r3, addr) \
    asm volatile("ldmatrix.sync.aligned.m8n8.x4.shared.b16 {%0,%1,%2,%3}, [%4];" \
                 : "=r"(r0), "=r"(r1), "=r"(r2), "=r"(r3) : "r"(addr))

__device__ __forceinline__ void cp16s(uint32_t daddr, const void* src, bool pred) {
    int sz = pred ? 16 : 0;
    asm volatile("cp.async.cg.shared.global [%0], [%1], 16, %2;\n"
                 :: "r"(daddr), "l"(src), "r"(sz));
}
__device__ __forceinline__ void cp_commit() { asm volatile("cp.async.commit_group;\n"); }
__device__ __forceinline__ void cp_wait2()  { asm volatile("cp.async.wait_group 2;\n"); }
__device__ __forceinline__ void cp_wait1()  { asm volatile("cp.async.wait_group 1;\n"); }
__device__ __forceinline__ void cp_wait0()  { asm volatile("cp.async.wait_group 0;\n"); }

__device__ __forceinline__ void mbar_init(uint32_t addr, uint32_t cnt) {
    asm volatile("mbarrier.init.shared.b64 [%0], %1;" :: "r"(addr), "r"(cnt) : "memory");
}
__device__ __forceinline__ void mbar_arrive(uint32_t addr) {
    asm volatile("mbarrier.arrive.shared.b64 _, [%0];" :: "r"(addr) : "memory");
}
__device__ __forceinline__ void mbar_wait(uint32_t addr, uint32_t parity) {
    asm volatile(
        "{\n\t.reg .pred P;\n\t"
        "W%=:\n\t"
        "mbarrier.try_wait.parity.acquire.cta.shared::cta.b64 P, [%0], %1, 0x989680;\n\t"
        "@!P bra W%=;\n\t}"
        :: "r"(addr), "r"(parity) : "memory");
}

// ---------------- prep A: wg + wu transpose/convert (stream s1) ----------------
__global__ void prep_wgu_kernel(const float* __restrict__ wg,
                                const float* __restrict__ wu) {
    __shared__ float t[32][33];
    int b = blockIdx.x;                 // 32768 blocks
    int z = b >> 11;                    // 0..15
    int ti = b & 2047;
    int e = z & 7;
    const float* s = (z < 8) ? wg : wu;
    __half* d = (z < 8) ? d_wgT : d_wuT;
    const int R = D_MODEL, C = DFF;
    int cx = ti & 63, ry = ti >> 6;     // 64 x 32 tile grid
    int c0 = cx * 32, r0 = ry * 32;
    s += (size_t)e * R * C;
    d += (size_t)e * R * C;
    int tx = threadIdx.x & 31, ty = threadIdx.x >> 5;
#pragma unroll
    for (int i = ty; i < 32; i += 8)
        t[i][tx] = s[(size_t)(r0 + i) * C + c0 + tx];
    __syncthreads();
#pragma unroll
    for (int i = ty; i < 32; i += 8)
        d[(size_t)(c0 + i) * R + r0 + tx] = __float2half_rn(t[tx][i]);
}

// ---------------- prep B: wd transpose/convert (stream s1, overlaps gemm1) -----
__global__ void prep_wd_kernel(const float* __restrict__ wd) {
    __shared__ float t[32][33];
    int b = blockIdx.x;                 // 16384 blocks
    int e = b >> 11;                    // 0..7
    int ti = b & 2047;
    const int R = DFF, C = D_MODEL;
    int cx = ti & 31, ry = ti >> 5;     // 32 x 64 tile grid
    int c0 = cx * 32, r0 = ry * 32;
    const float* s = wd + (size_t)e * R * C;
    __half* d = d_wdT + (size_t)e * R * C;
    int tx = threadIdx.x & 31, ty = threadIdx.x >> 5;
#pragma unroll
    for (int i = ty; i < 32; i += 8)
        t[i][tx] = s[(size_t)(r0 + i) * C + c0 + tx];
    __syncthreads();
#pragma unroll
    for (int i = ty; i < 32; i += 8)
        d[(size_t)(c0 + i) * R + r0 + tx] = __float2half_rn(t[tx][i]);
}

// ---------------- prep X: init + x convert + router (stream 0) -----------------
__global__ void prep_x_kernel(const float* __restrict__ x,
                              const float* __restrict__ rw,
                              const float* __restrict__ rb,
                              float* __restrict__ out) {
    int tid = threadIdx.x;
    int b = blockIdx.x;
    if (b < 512) {
        // router: 8 warps = 8 tokens per block
        int warp = tid >> 5, lane = tid & 31;
        int gw = b * 8 + warp;
        const float* xr = x + (size_t)gw * D_MODEL;
        float acc[NROUTED];
#pragma unroll
        for (int j = 0; j < NROUTED; j++) acc[j] = 0.f;
        for (int k = lane; k < D_MODEL; k += 32) {
            float xv = xr[k];
            const float* w = rw + k * NROUTED;
#pragma unroll
            for (int j = 0; j < NROUTED; j++) acc[j] += xv * w[j];
        }
#pragma unroll
        for (int j = 0; j < NROUTED; j++) {
#pragma unroll
            for (int o = 16; o > 0; o >>= 1)
                acc[j] += __shfl_xor_sync(0xffffffffu, acc[j], o);
        }
        if (lane == 0) {
            float lg[NROUTED];
#pragma unroll
            for (int j = 0; j < NROUTED; j++) lg[j] = acc[j] + rb[j];
            int i1 = 0;
#pragma unroll
            for (int j = 1; j < NROUTED; j++) if (lg[j] > lg[i1]) i1 = j;
            int i2 = (i1 == 0) ? 1 : 0;
#pragma unroll
            for (int j = 0; j < NROUTED; j++)
                if (j != i1 && lg[j] > lg[i2]) i2 = j;
            float m  = fmaxf(lg[i1], lg[i2]);
            float e1 = expf(lg[i1] - m), e2 = expf(lg[i2] - m);
            float s  = e1 + e2;
            d_topi[gw * 2] = i1;  d_topi[gw * 2 + 1] = i2;
            d_topw[gw * 2] = e1 / s;  d_topw[gw * 2 + 1] = e2 / s;
            atomicAdd(&d_cnt[i1], 1);
            atomicAdd(&d_cnt[i2], 1);
        }
    }
    // init duty: all blocks, grid-stride
    int stride = gridDim.x * blockDim.x;
    int i = b * blockDim.x + tid;
    for (int j = i; j < T_TOK * D_MODEL; j += stride) {
        out[j] = 0.f;
        d_X[j] = __float2half_rn(x[j]);
    }
    for (int j = i; j < R_MAX; j += stride) {
        if (j < T_TOK) { d_tok[j] = j;  d_wrow[j] = 1.f; }
        else           { d_tok[j] = -1; d_wrow[j] = 0.f; }
    }
}

// ---------------- offsets + fill (single block) --------------------------------
__global__ void offsfill_kernel() {
    int tid = threadIdx.x;
    if (tid == 0) {
        int base = T_TOK;
        for (int j = 0; j < NROUTED; j++) {
            d_off[j] = base;
            base += ((d_cnt[j] + BM - 1) / BM) * BM;
            d_cnt[j] = 0;
        }
        d_off[7] = base;
    }
    __syncthreads();
    for (int i = tid; i < T_TOK * 2; i += blockDim.x) {
        int t = i >> 1;
        int e = d_topi[i];
        float w = d_topw[i];
        int p = atomicAdd(&d_cnt2[e], 1);
        int r = d_off[e] + p;
        d_tok[r]  = t;
        d_wrow[r] = w;
    }
    __syncthreads();
    if (tid < NROUTED) d_cnt2[tid] = 0;
}

__device__ __forceinline__ int tile_expert(int row0) {
    if (row0 < T_TOK) return 0;
    int e = 0;
#pragma unroll
    for (int j = 0; j < NROUTED; j++)
        if (row0 >= d_off[j] && row0 < d_off[j + 1]) e = j + 1;
    return e;
}

// ---------------- gemm1: 256 thr, 8 warps (2m x 4n), warp tile 64x32 -----------
#define G1_STG  (3 * TILEB)
#define G1_SMEM (NSTAGE * G1_STG)        // 165888 B

__global__ __launch_bounds__(256, 1) void gemm1_kernel() {
    int row0 = blockIdx.x * BM;
    if (row0 >= d_off[7]) return;
    int e = tile_expert(row0);
    const __half* bg = d_wgT + (size_t)e * DFF * D_MODEL;
    const __half* bu = d_wuT + (size_t)e * DFF * D_MODEL;
    int n0 = blockIdx.y * 128;

    extern __shared__ char raw[];
    uint32_t base = smem_u32(raw);
    __shared__ int stok[128];
    __shared__ __align__(8) uint64_t s_mb[2 * NSTAGE];

    int tid = threadIdx.x, warp = tid >> 5, lane = tid & 31;
    if (tid < 128) stok[tid] = d_tok[row0 + tid];
    uint32_t mbF = smem_u32(&s_mb[0]);
    uint32_t mbE = smem_u32(&s_mb[NSTAGE]);
    if (tid < NSTAGE)              mbar_init(mbF + tid * 8, 8);
    else if (tid < 2 * NSTAGE)     mbar_init(mbE + (tid - NSTAGE) * 8, 8);
    __syncthreads();

    int wm = (warp >> 2) * 64, wn = (warp & 3) * 32;

    int ar[4], ac[4]; const __half* asrc[4]; const __half* gsrc[4]; const __half* usrc[4];
    bool apred[4];
#pragma unroll
    for (int i = 0; i < 4; i++) {
        int f = tid + i * 256;
        ar[i] = f >> 3; ac[i] = f & 7;
        int tok = stok[ar[i]];
        apred[i] = (tok >= 0);
        asrc[i] = d_X + (size_t)(apred[i] ? tok : 0) * D_MODEL + ac[i] * 8;
        gsrc[i] = bg + (size_t)(n0 + ar[i]) * D_MODEL + ac[i] * 8;
        usrc[i] = bu + (size_t)(n0 + ar[i]) * D_MODEL + ac[i] * 8;
    }

    auto issue = [&](int s, int ktile) {
        uint32_t S = base + s * G1_STG;
        int k0 = ktile * BK;
#pragma unroll
        for (int i = 0; i < 4; i++) {
            uint32_t d0 = S + ar[i] * ROWB + ac[i] * 16;
            cp16s(d0,             asrc[i] + (apred[i] ? k0 : 0), apred[i]);
            cp16s(d0 + TILEB,     gsrc[i] + k0, true);
            cp16s(d0 + 2 * TILEB, usrc[i] + k0, true);
        }
        cp_commit();
    };

    int arow = 8 * ((lane >> 3) & 1) + (lane & 7);
    int abyt = 16 * (lane >> 4);
    uint32_t aoff[4];
#pragma unroll
    for (int mi = 0; mi < 4; mi++)
        aoff[mi] = (uint32_t)((wm + mi * 16 + arow) * ROWB + abyt);
    int brow = 8 * (lane >> 4) + (lane & 7);
    int bbyt = 16 * ((lane >> 3) & 1);
    uint32_t goff[2], uoff[2];
#pragma unroll
    for (int p = 0; p < 2; p++) {
        uint32_t o = (uint32_t)((wn + p * 16 + brow) * ROWB + bbyt);
        goff[p] = TILEB + o;
        uoff[p] = 2 * TILEB + o;
    }

    float accG[4][4][4], accU[4][4][4];
#pragma unroll
    for (int mi = 0; mi < 4; mi++)
#pragma unroll
        for (int ni = 0; ni < 4; ni++)
#pragma unroll
            for (int r = 0; r < 4; r++) { accG[mi][ni][r] = 0.f; accU[mi][ni][r] = 0.f; }

    const int KT = D_MODEL / BK;   // 16
#pragma unroll
    for (int p = 0; p < NSTAGE; p++) issue(p, p);

    for (int kt = 0; kt < KT; kt++) {
        int s = kt % NSTAGE;
        uint32_t ph = (uint32_t)((kt / NSTAGE) & 1);
        uint32_t fB = mbF + s * 8, eB = mbE + s * 8;

        if (kt < KT - 2) cp_wait2(); else if (kt == KT - 2) cp_wait1(); else cp_wait0();
        __syncwarp();
        if (lane == 0) mbar_arrive(fB);
        mbar_wait(fB, ph);

        uint32_t S = base + s * G1_STG;
#pragma unroll
        for (int ks = 0; ks < 4; ks++) {
            uint32_t a[4][4];
#pragma unroll
            for (int mi = 0; mi < 4; mi++)
                LDSM4(a[mi][0], a[mi][1], a[mi][2], a[mi][3], S + aoff[mi] + ks * 32);
#pragma unroll
            for (int p = 0; p < 2; p++) {
                uint32_t g4[4], u4[4];
                LDSM4(g4[0], g4[1], g4[2], g4[3], S + goff[p] + ks * 32);
                LDSM4(u4[0], u4[1], u4[2], u4[3], S + uoff[p] + ks * 32);
#pragma unroll
                for (int mi = 0; mi < 4; mi++) {
                    hmma(accG[mi][2 * p],     a[mi], g4 + 0);
                    hmma(accG[mi][2 * p + 1], a[mi], g4 + 2);
                    hmma(accU[mi][2 * p],     a[mi], u4 + 0);
                    hmma(accU[mi][2 * p + 1], a[mi], u4 + 2);
                }
            }
        }
        __syncwarp();
        if (lane == 0) mbar_arrive(eB);

        if (kt + NSTAGE < KT) {
            mbar_wait(eB, ph);
            issue(s, kt + NSTAGE);
        }
    }

#pragma unroll
    for (int mi = 0; mi < 4; mi++)
#pragma unroll
        for (int ni = 0; ni < 4; ni++)
#pragma unroll
            for (int rr = 0; rr < 4; rr++) {
                int rl = wm + mi * 16 + (lane >> 2) + ((rr >= 2) ? 8 : 0);
                if (stok[rl] < 0) continue;
                int col = n0 + wn + ni * 8 + 2 * (lane & 3) + (rr & 1);
                float g = accG[mi][ni][rr], u = accU[mi][ni][rr];
                float h = (g / (1.f + __expf(-g))) * u;
                d_H[(size_t)(row0 + rl) * DFF + col] = __float2half_rn(h);
            }
}

// ---------------- gemm2: 256 thr, warp tile 64x32, down GEMM + scatter ---------
#define G2_STG  (2 * TILEB)
#define G2_SMEM (NSTAGE * G2_STG)        // 110592 B

__global__ __launch_bounds__(256, 1) void gemm2_kernel(float* __restrict__ out) {
    int row0 = blockIdx.x * BM;
    if (row0 >= d_off[7]) return;
    int e = tile_expert(row0);
    const __half* bw = d_wdT + (size_t)e * DFF * D_MODEL;
    int n0 = blockIdx.y * 128;

    extern __shared__ char raw[];
    uint32_t base = smem_u32(raw);
    __shared__ int stok[128];
    __shared__ float swt[128];
    __shared__ __align__(8) uint64_t s_mb[2 * NSTAGE];

    int tid = threadIdx.x, warp = tid >> 5, lane = tid & 31;
    if (tid < 128) { stok[tid] = d_tok[row0 + tid]; swt[tid] = d_wrow[row0 + tid]; }
    uint32_t mbF = smem_u32(&s_mb[0]);
    uint32_t mbE = smem_u32(&s_mb[NSTAGE]);
    if (tid < NSTAGE)              mbar_init(mbF + tid * 8, 8);
    else if (tid < 2 * NSTAGE)     mbar_init(mbE + (tid - NSTAGE) * 8, 8);
    __syncthreads();

    int wm = (warp >> 2) * 64, wn = (warp & 3) * 32;

    int ar[4], ac[4]; bool apred[4]; const __half* asrc[4]; const __half* bsrc[4];
#pragma unroll
    for (int i = 0; i < 4; i++) {
        int f = tid + i * 256;
        ar[i] = f >> 3; ac[i] = f & 7;
        apred[i] = (stok[ar[i]] >= 0);
        asrc[i] = d_H + (size_t)(row0 + ar[i]) * DFF + ac[i] * 8;
        bsrc[i] = bw + (size_t)(n0 + ar[i]) * DFF + ac[i] * 8;
    }

    auto issue = [&](int s, int ktile) {
        uint32_t S = base + s * G2_STG;
        int k0 = ktile * BK;
#pragma unroll
        for (int i = 0; i < 4; i++) {
            uint32_t d0 = S + ar[i] * ROWB + ac[i] * 16;
            cp16s(d0,         asrc[i] + (apred[i] ? k0 : 0), apred[i]);
            cp16s(d0 + TILEB, bsrc[i] + k0, true);
        }
        cp_commit();
    };

    int arow = 8 * ((lane >> 3) & 1) + (lane & 7);
    int abyt = 16 * (lane >> 4);
    uint32_t aoff[4];
#pragma unroll
    for (int mi = 0; mi < 4; mi++)
        aoff[mi] = (uint32_t)((wm + mi * 16 + arow) * ROWB + abyt);
    int brow = 8 * (lane >> 4) + (lane & 7);
    int bbyt = 16 * ((lane >> 3) & 1);
    uint32_t boff[2];
#pragma unroll
    for (int p = 0; p < 2; p++)
        boff[p] = TILEB + (uint32_t)((wn + p * 16 + brow) * ROWB + bbyt);

    float acc[4][4][4];
#pragma unroll
    for (int mi = 0; mi < 4; mi++)
#pragma unroll
        for (int ni = 0; ni < 4; ni++)
#pragma unroll
            for (int r = 0; r < 4; r++) acc[mi][ni][r] = 0.f;

    const int KT = DFF / BK;   // 32
#pragma unroll
    for (int p = 0; p < NSTAGE; p++) issue(p, p);

    for (int kt = 0; kt < KT; kt++) {
        int s = kt % NSTAGE;
        uint32_t ph = (uint32_t)((kt / NSTAGE) & 1);
        uint32_t fB = mbF + s * 8, eB = mbE + s * 8;

        if (kt < KT - 2) cp_wait2(); else if (kt == KT - 2) cp_wait1(); else cp_wait0();
        __syncwarp();
        if (lane == 0) mbar_arrive(fB);
        mbar_wait(fB, ph);

        uint32_t S = base + s * G2_STG;
#pragma unroll
        for (int ks = 0; ks < 4; ks++) {
            uint32_t a[4][4];
#pragma unroll
            for (int mi = 0; mi < 4; mi++)
                LDSM4(a[mi][0], a[mi][1], a[mi][2], a[mi][3], S + aoff[mi] + ks * 32);
#pragma unroll
            for (int p = 0; p < 2; p++) {
                uint32_t b4[4];
                LDSM4(b4[0], b4[1], b4[2], b4[3], S + boff[p] + ks * 32);
#pragma unroll
                for (int mi = 0; mi < 4; mi++) {
                    hmma(acc[mi][2 * p],     a[mi], b4 + 0);
                    hmma(acc[mi][2 * p + 1], a[mi], b4 + 2);
                }
            }
        }
        __syncwarp();
        if (lane == 0) mbar_arrive(eB);

        if (kt + NSTAGE < KT) {
            mbar_wait(eB, ph);
            issue(s, kt + NSTAGE);
        }
    }

#pragma unroll
    for (int mi = 0; mi < 4; mi++)
#pragma unroll
        for (int ni = 0; ni < 4; ni++)
#pragma unroll
            for (int rr = 0; rr < 4; rr++) {
                int rl = wm + mi * 16 + (lane >> 2) + ((rr >= 2) ? 8 : 0);
                int tok = stok[rl];
                if (tok < 0) continue;
                int col = n0 + wn + ni * 8 + 2 * (lane & 3) + (rr & 1);
                atomicAdd(out + (size_t)tok * D_MODEL + col, swt[rl] * acc[mi][ni][rr]);
            }
}

// ---------------- launch: forked-stream graph ----------------------------------
extern "C" void kernel_launch(void* const* d_in, const int* in_sizes, int n_in,
                              void* d_out, int out_size) {
    const float* x  = (const float*)d_in[0];
    const float* rw = (const float*)d_in[1];
    const float* rb = (const float*)d_in[2];
    const float* wg = (const float*)d_in[3];
    const float* wu = (const float*)d_in[4];
    const float* wd = (const float*)d_in[5];
    float* out = (float*)d_out;
    (void)in_sizes; (void)n_in; (void)out_size;

    static cudaStream_t s1 = nullptr;
    static cudaEvent_t evFork = nullptr, evGU = nullptr, evWd = nullptr;
    if (!s1) {
        cudaStreamCreateWithFlags(&s1, cudaStreamNonBlocking);
        cudaEventCreateWithFlags(&evFork, cudaEventDisableTiming);
        cudaEventCreateWithFlags(&evGU,   cudaEventDisableTiming);
        cudaEventCreateWithFlags(&evWd,   cudaEventDisableTiming);
        cudaFuncSetAttribute(gemm1_kernel, cudaFuncAttributeMaxDynamicSharedMemorySize, G1_SMEM);
        cudaFuncSetAttribute(gemm2_kernel, cudaFuncAttributeMaxDynamicSharedMemorySize, G2_SMEM);
    }

    // fork: weight conversion runs on s1, concurrent with router/init and gemm1
    cudaEventRecord(evFork, 0);
    cudaStreamWaitEvent(s1, evFork, 0);

    prep_wgu_kernel<<<32768, 256, 0, s1>>>(wg, wu);              // launch 1
    cudaEventRecord(evGU, s1);

    prep_x_kernel<<<1024, 256>>>(x, rw, rb, out);                // launch 2 (stream 0)
    offsfill_kernel<<<1, 1024>>>();                              // launch 3

    cudaStreamWaitEvent(0, evGU, 0);                             // gemm1 needs wgT/wuT
    gemm1_kernel<<<dim3(NTILES_M, DFF / 128), 256, G1_SMEM>>>(); // launch 4 (ncu window)

    prep_wd_kernel<<<16384, 256, 0, s1>>>(wd);                   // launch 5: overlaps gemm1
    cudaEventRecord(evWd, s1);

    cudaStreamWaitEvent(0, evWd, 0);                             // gemm2 needs wdT (join s1)
    gemm2_kernel<<<dim3(NTILES_M, D_MODEL / 128), 256, G2_SMEM>>>(out);  // launch 6
}

// round 10
// speedup vs baseline: 5.7663x; 1.0024x over previous
#include <cuda_runtime.h>
#include <cuda_fp16.h>
#include <cstdint>

// Problem constants
#define T_TOK   4096
#define D_MODEL 1024
#define DFF     2048
#define NROUTED 7
#define BM      128
#define BK      64
#define NTILES_M 104
#define NTILES_H 52
#define R_MAX   (NTILES_M * BM)

// smem tile: 128 rows x 128B data (64 fp16), stride 144B -> conflict-free ldmatrix
#define ROWB   144
#define TILEB  (128 * ROWB)      // 18432 B
#define NSTAGE 3

// ---------------- scratch (static device globals; no allocations) -------------
__device__ __half d_H[(size_t)R_MAX * DFF];
__device__ __half d_X[(size_t)T_TOK * D_MODEL];
__device__ __half d_wgT[(size_t)8 * DFF * D_MODEL];   // [E][N=DFF][K=D]
__device__ __half d_wuT[(size_t)8 * DFF * D_MODEL];
__device__ __half d_wdT[(size_t)8 * D_MODEL * DFF];   // [E][N=D][K=DFF]
__device__ int    d_tok[R_MAX];
__device__ float  d_wrow[R_MAX];
__device__ int    d_off[8];
__device__ int    d_cnt[NROUTED];
__device__ int    d_cnt2[NROUTED];
__device__ int    d_topi[T_TOK * 2];
__device__ float  d_topw[T_TOK * 2];

// ---------------- helpers ----------------------------------------------------
__device__ __forceinline__ uint32_t smem_u32(const void* p) {
    uint32_t a;
    asm("{ .reg .u64 t; cvta.to.shared.u64 t, %1; cvt.u32.u64 %0, t; }"
        : "=r"(a) : "l"(p));
    return a;
}

__device__ __forceinline__ void hmma(float c[4], const uint32_t a[4], const uint32_t b[2]) {
    asm volatile(
        "mma.sync.aligned.m16n8k16.row.col.f32.f16.f16.f32 "
        "{%0,%1,%2,%3}, {%4,%5,%6,%7}, {%8,%9}, {%0,%1,%2,%3};\n"
        : "+f"(c[0]), "+f"(c[1]), "+f"(c[2]), "+f"(c[3])
        : "r"(a[0]), "r"(a[1]), "r"(a[2]), "r"(a[3]), "r"(b[0]), "r"(b[1]));
}

#define LDSM4(r0, r1, r2, r3, addr) \
    asm volatile("ldmatrix.sync.aligned.m8n8.x4.shared.b16 {%0,%1,%2,%3}, [%4];" \
                 : "=r"(r0), "=r"(r1), "=r"(r2), "=r"(r3) : "r"(addr))

__device__ __forceinline__ void cp16s(uint32_t daddr, const void* src, bool pred) {
    int sz = pred ? 16 : 0;
    asm volatile("cp.async.cg.shared.global [%0], [%1], 16, %2;\n"
                 :: "r"(daddr), "l"(src), "r"(sz));
}
__device__ __forceinline__ void cp_commit() { asm volatile("cp.async.commit_group;\n"); }
__device__ __forceinline__ void cp_wait2()  { asm volatile("cp.async.wait_group 2;\n"); }
__device__ __forceinline__ void cp_wait1()  { asm volatile("cp.async.wait_group 1;\n"); }
__device__ __forceinline__ void cp_wait0()  { asm volatile("cp.async.wait_group 0;\n"); }

__device__ __forceinline__ void mbar_init(uint32_t addr, uint32_t cnt) {
    asm volatile("mbarrier.init.shared.b64 [%0], %1;" :: "r"(addr), "r"(cnt) : "memory");
}
__device__ __forceinline__ void mbar_arrive(uint32_t addr) {
    asm volatile("mbarrier.arrive.shared.b64 _, [%0];" :: "r"(addr) : "memory");
}
__device__ __forceinline__ void mbar_wait(uint32_t addr, uint32_t parity) {
    asm volatile(
        "{\n\t.reg .pred P;\n\t"
        "W%=:\n\t"
        "mbarrier.try_wait.parity.acquire.cta.shared::cta.b64 P, [%0], %1, 0x989680;\n\t"
        "@!P bra W%=;\n\t}"
        :: "r"(addr), "r"(parity) : "memory");
}

// ---------------- prep A: wg + wu transpose/convert (stream s1) ----------------
__global__ void prep_wgu_kernel(const float* __restrict__ wg,
                                const float* __restrict__ wu) {
    __shared__ float t[32][33];
    int b = blockIdx.x;                 // 32768 blocks
    int z = b >> 11;                    // 0..15
    int ti = b & 2047;
    int e = z & 7;
    const float* s = (z < 8) ? wg : wu;
    __half* d = (z < 8) ? d_wgT : d_wuT;
    const int R = D_MODEL, C = DFF;
    int cx = ti & 63, ry = ti >> 6;     // 64 x 32 tile grid
    int c0 = cx * 32, r0 = ry * 32;
    s += (size_t)e * R * C;
    d += (size_t)e * R * C;
    int tx = threadIdx.x & 31, ty = threadIdx.x >> 5;
#pragma unroll
    for (int i = ty; i < 32; i += 8)
        t[i][tx] = s[(size_t)(r0 + i) * C + c0 + tx];
    __syncthreads();
#pragma unroll
    for (int i = ty; i < 32; i += 8)
        d[(size_t)(c0 + i) * R + r0 + tx] = __float2half_rn(t[tx][i]);
}

// ---------------- prep B: wd transpose/convert (stream s1) ---------------------
__global__ void prep_wd_kernel(const float* __restrict__ wd) {
    __shared__ float t[32][33];
    int b = blockIdx.x;                 // 16384 blocks
    int e = b >> 11;                    // 0..7
    int ti = b & 2047;
    const int R = DFF, C = D_MODEL;
    int cx = ti & 31, ry = ti >> 5;     // 32 x 64 tile grid
    int c0 = cx * 32, r0 = ry * 32;
    const float* s = wd + (size_t)e * R * C;
    __half* d = d_wdT + (size_t)e * R * C;
    int tx = threadIdx.x & 31, ty = threadIdx.x >> 5;
#pragma unroll
    for (int i = ty; i < 32; i += 8)
        t[i][tx] = s[(size_t)(r0 + i) * C + c0 + tx];
    __syncthreads();
#pragma unroll
    for (int i = ty; i < 32; i += 8)
        d[(size_t)(c0 + i) * R + r0 + tx] = __float2half_rn(t[tx][i]);
}

// ---------------- prep X: init + x convert + router (stream 0) -----------------
__global__ void prep_x_kernel(const float* __restrict__ x,
                              const float* __restrict__ rw,
                              const float* __restrict__ rb,
                              float* __restrict__ out) {
    int tid = threadIdx.x;
    int b = blockIdx.x;
    if (b < 512) {
        int warp = tid >> 5, lane = tid & 31;
        int gw = b * 8 + warp;
        const float* xr = x + (size_t)gw * D_MODEL;
        float acc[NROUTED];
#pragma unroll
        for (int j = 0; j < NROUTED; j++) acc[j] = 0.f;
        for (int k = lane; k < D_MODEL; k += 32) {
            float xv = xr[k];
            const float* w = rw + k * NROUTED;
#pragma unroll
            for (int j = 0; j < NROUTED; j++) acc[j] += xv * w[j];
        }
#pragma unroll
        for (int j = 0; j < NROUTED; j++) {
#pragma unroll
            for (int o = 16; o > 0; o >>= 1)
                acc[j] += __shfl_xor_sync(0xffffffffu, acc[j], o);
        }
        if (lane == 0) {
            float lg[NROUTED];
#pragma unroll
            for (int j = 0; j < NROUTED; j++) lg[j] = acc[j] + rb[j];
            int i1 = 0;
#pragma unroll
            for (int j = 1; j < NROUTED; j++) if (lg[j] > lg[i1]) i1 = j;
            int i2 = (i1 == 0) ? 1 : 0;
#pragma unroll
            for (int j = 0; j < NROUTED; j++)
                if (j != i1 && lg[j] > lg[i2]) i2 = j;
            float m  = fmaxf(lg[i1], lg[i2]);
            float e1 = expf(lg[i1] - m), e2 = expf(lg[i2] - m);
            float s  = e1 + e2;
            d_topi[gw * 2] = i1;  d_topi[gw * 2 + 1] = i2;
            d_topw[gw * 2] = e1 / s;  d_topw[gw * 2 + 1] = e2 / s;
            atomicAdd(&d_cnt[i1], 1);
            atomicAdd(&d_cnt[i2], 1);
        }
    }
    int stride = gridDim.x * blockDim.x;
    int i = b * blockDim.x + tid;
    for (int j = i; j < T_TOK * D_MODEL; j += stride) {
        out[j] = 0.f;
        d_X[j] = __float2half_rn(x[j]);
    }
    for (int j = i; j < R_MAX; j += stride) {
        if (j < T_TOK) { d_tok[j] = j;  d_wrow[j] = 1.f; }
        else           { d_tok[j] = -1; d_wrow[j] = 0.f; }
    }
}

// ---------------- offsets + fill (single block) --------------------------------
__global__ void offsfill_kernel() {
    int tid = threadIdx.x;
    if (tid == 0) {
        int base = T_TOK;
        for (int j = 0; j < NROUTED; j++) {
            d_off[j] = base;
            base += ((d_cnt[j] + BM - 1) / BM) * BM;
            d_cnt[j] = 0;
        }
        d_off[7] = base;
    }
    __syncthreads();
    for (int i = tid; i < T_TOK * 2; i += blockDim.x) {
        int t = i >> 1;
        int e = d_topi[i];
        float w = d_topw[i];
        int p = atomicAdd(&d_cnt2[e], 1);
        int r = d_off[e] + p;
        d_tok[r]  = t;
        d_wrow[r] = w;
    }
    __syncthreads();
    if (tid < NROUTED) d_cnt2[tid] = 0;
}

__device__ __forceinline__ int tile_expert(int row0) {
    if (row0 < T_TOK) return 0;
    int e = 0;
#pragma unroll
    for (int j = 0; j < NROUTED; j++)
        if (row0 >= d_off[j] && row0 < d_off[j + 1]) e = j + 1;
    return e;
}

// ---------------- gemm1: 256 thr, 8 warps (2m x 4n), warp tile 64x32 -----------
#define G1_STG  (3 * TILEB)
#define G1_SMEM (NSTAGE * G1_STG)        // 165888 B

__global__ __launch_bounds__(256, 1) void gemm1_kernel(int xoff) {
    int row0 = (blockIdx.x + xoff) * BM;
    if (row0 >= d_off[7]) return;
    int e = tile_expert(row0);
    const __half* bg = d_wgT + (size_t)e * DFF * D_MODEL;
    const __half* bu = d_wuT + (size_t)e * DFF * D_MODEL;
    int n0 = blockIdx.y * 128;

    extern __shared__ char raw[];
    uint32_t base = smem_u32(raw);
    __shared__ int stok[128];
    __shared__ __align__(8) uint64_t s_mb[2 * NSTAGE];

    int tid = threadIdx.x, warp = tid >> 5, lane = tid & 31;
    if (tid < 128) stok[tid] = d_tok[row0 + tid];
    uint32_t mbF = smem_u32(&s_mb[0]);
    uint32_t mbE = smem_u32(&s_mb[NSTAGE]);
    if (tid < NSTAGE)              mbar_init(mbF + tid * 8, 8);
    else if (tid < 2 * NSTAGE)     mbar_init(mbE + (tid - NSTAGE) * 8, 8);
    __syncthreads();

    int wm = (warp >> 2) * 64, wn = (warp & 3) * 32;

    int ar[4], ac[4]; const __half* asrc[4]; const __half* gsrc[4]; const __half* usrc[4];
    bool apred[4];
#pragma unroll
    for (int i = 0; i < 4; i++) {
        int f = tid + i * 256;
        ar[i] = f >> 3; ac[i] = f & 7;
        int tok = stok[ar[i]];
        apred[i] = (tok >= 0);
        asrc[i] = d_X + (size_t)(apred[i] ? tok : 0) * D_MODEL + ac[i] * 8;
        gsrc[i] = bg + (size_t)(n0 + ar[i]) * D_MODEL + ac[i] * 8;
        usrc[i] = bu + (size_t)(n0 + ar[i]) * D_MODEL + ac[i] * 8;
    }

    auto issue = [&](int s, int ktile) {
        uint32_t S = base + s * G1_STG;
        int k0 = ktile * BK;
#pragma unroll
        for (int i = 0; i < 4; i++) {
            uint32_t d0 = S + ar[i] * ROWB + ac[i] * 16;
            cp16s(d0,             asrc[i] + (apred[i] ? k0 : 0), apred[i]);
            cp16s(d0 + TILEB,     gsrc[i] + k0, true);
            cp16s(d0 + 2 * TILEB, usrc[i] + k0, true);
        }
        cp_commit();
    };

    int arow = 8 * ((lane >> 3) & 1) + (lane & 7);
    int abyt = 16 * (lane >> 4);
    uint32_t aoff[4];
#pragma unroll
    for (int mi = 0; mi < 4; mi++)
        aoff[mi] = (uint32_t)((wm + mi * 16 + arow) * ROWB + abyt);
    int brow = 8 * (lane >> 4) + (lane & 7);
    int bbyt = 16 * ((lane >> 3) & 1);
    uint32_t goff[2], uoff[2];
#pragma unroll
    for (int p = 0; p < 2; p++) {
        uint32_t o = (uint32_t)((wn + p * 16 + brow) * ROWB + bbyt);
        goff[p] = TILEB + o;
        uoff[p] = 2 * TILEB + o;
    }

    float accG[4][4][4], accU[4][4][4];
#pragma unroll
    for (int mi = 0; mi < 4; mi++)
#pragma unroll
        for (int ni = 0; ni < 4; ni++)
#pragma unroll
            for (int r = 0; r < 4; r++) { accG[mi][ni][r] = 0.f; accU[mi][ni][r] = 0.f; }

    const int KT = D_MODEL / BK;   // 16
#pragma unroll
    for (int p = 0; p < NSTAGE; p++) issue(p, p);

    for (int kt = 0; kt < KT; kt++) {
        int s = kt % NSTAGE;
        uint32_t ph = (uint32_t)((kt / NSTAGE) & 1);
        uint32_t fB = mbF + s * 8, eB = mbE + s * 8;

        if (kt < KT - 2) cp_wait2(); else if (kt == KT - 2) cp_wait1(); else cp_wait0();
        __syncwarp();
        if (lane == 0) mbar_arrive(fB);
        mbar_wait(fB, ph);

        uint32_t S = base + s * G1_STG;
#pragma unroll
        for (int ks = 0; ks < 4; ks++) {
            uint32_t a[4][4];
#pragma unroll
            for (int mi = 0; mi < 4; mi++)
                LDSM4(a[mi][0], a[mi][1], a[mi][2], a[mi][3], S + aoff[mi] + ks * 32);
#pragma unroll
            for (int p = 0; p < 2; p++) {
                uint32_t g4[4], u4[4];
                LDSM4(g4[0], g4[1], g4[2], g4[3], S + goff[p] + ks * 32);
                LDSM4(u4[0], u4[1], u4[2], u4[3], S + uoff[p] + ks * 32);
#pragma unroll
                for (int mi = 0; mi < 4; mi++) {
                    hmma(accG[mi][2 * p],     a[mi], g4 + 0);
                    hmma(accG[mi][2 * p + 1], a[mi], g4 + 2);
                    hmma(accU[mi][2 * p],     a[mi], u4 + 0);
                    hmma(accU[mi][2 * p + 1], a[mi], u4 + 2);
                }
            }
        }
        __syncwarp();
        if (lane == 0) mbar_arrive(eB);

        if (kt + NSTAGE < KT) {
            mbar_wait(eB, ph);
            issue(s, kt + NSTAGE);
        }
    }

#pragma unroll
    for (int mi = 0; mi < 4; mi++)
#pragma unroll
        for (int ni = 0; ni < 4; ni++)
#pragma unroll
            for (int rr = 0; rr < 4; rr++) {
                int rl = wm + mi * 16 + (lane >> 2) + ((rr >= 2) ? 8 : 0);
                if (stok[rl] < 0) continue;
                int col = n0 + wn + ni * 8 + 2 * (lane & 3) + (rr & 1);
                float g = accG[mi][ni][rr], u = accU[mi][ni][rr];
                float h = (g / (1.f + __expf(-g))) * u;
                d_H[(size_t)(row0 + rl) * DFF + col] = __float2half_rn(h);
            }
}

// ---------------- gemm2: 256 thr, warp tile 64x32, down GEMM + scatter ---------
#define G2_STG  (2 * TILEB)
#define G2_SMEM (NSTAGE * G2_STG)        // 110592 B

__global__ __launch_bounds__(256, 1) void gemm2_kernel(float* __restrict__ out, int xoff) {
    int row0 = (blockIdx.x + xoff) * BM;
    if (row0 >= d_off[7]) return;
    int e = tile_expert(row0);
    const __half* bw = d_wdT + (size_t)e * DFF * D_MODEL;
    int n0 = blockIdx.y * 128;

    extern __shared__ char raw[];
    uint32_t base = smem_u32(raw);
    __shared__ int stok[128];
    __shared__ float swt[128];
    __shared__ __align__(8) uint64_t s_mb[2 * NSTAGE];

    int tid = threadIdx.x, warp = tid >> 5, lane = tid & 31;
    if (tid < 128) { stok[tid] = d_tok[row0 + tid]; swt[tid] = d_wrow[row0 + tid]; }
    uint32_t mbF = smem_u32(&s_mb[0]);
    uint32_t mbE = smem_u32(&s_mb[NSTAGE]);
    if (tid < NSTAGE)              mbar_init(mbF + tid * 8, 8);
    else if (tid < 2 * NSTAGE)     mbar_init(mbE + (tid - NSTAGE) * 8, 8);
    __syncthreads();

    int wm = (warp >> 2) * 64, wn = (warp & 3) * 32;

    int ar[4], ac[4]; bool apred[4]; const __half* asrc[4]; const __half* bsrc[4];
#pragma unroll
    for (int i = 0; i < 4; i++) {
        int f = tid + i * 256;
        ar[i] = f >> 3; ac[i] = f & 7;
        apred[i] = (stok[ar[i]] >= 0);
        asrc[i] = d_H + (size_t)(row0 + ar[i]) * DFF + ac[i] * 8;
        bsrc[i] = bw + (size_t)(n0 + ar[i]) * DFF + ac[i] * 8;
    }

    auto issue = [&](int s, int ktile) {
        uint32_t S = base + s * G2_STG;
        int k0 = ktile * BK;
#pragma unroll
        for (int i = 0; i < 4; i++) {
            uint32_t d0 = S + ar[i] * ROWB + ac[i] * 16;
            cp16s(d0,         asrc[i] + (apred[i] ? k0 : 0), apred[i]);
            cp16s(d0 + TILEB, bsrc[i] + k0, true);
        }
        cp_commit();
    };

    int arow = 8 * ((lane >> 3) & 1) + (lane & 7);
    int abyt = 16 * (lane >> 4);
    uint32_t aoff[4];
#pragma unroll
    for (int mi = 0; mi < 4; mi++)
        aoff[mi] = (uint32_t)((wm + mi * 16 + arow) * ROWB + abyt);
    int brow = 8 * (lane >> 4) + (lane & 7);
    int bbyt = 16 * ((lane >> 3) & 1);
    uint32_t boff[2];
#pragma unroll
    for (int p = 0; p < 2; p++)
        boff[p] = TILEB + (uint32_t)((wn + p * 16 + brow) * ROWB + bbyt);

    float acc[4][4][4];
#pragma unroll
    for (int mi = 0; mi < 4; mi++)
#pragma unroll
        for (int ni = 0; ni < 4; ni++)
#pragma unroll
            for (int r = 0; r < 4; r++) acc[mi][ni][r] = 0.f;

    const int KT = DFF / BK;   // 32
#pragma unroll
    for (int p = 0; p < NSTAGE; p++) issue(p, p);

    for (int kt = 0; kt < KT; kt++) {
        int s = kt % NSTAGE;
        uint32_t ph = (uint32_t)((kt / NSTAGE) & 1);
        uint32_t fB = mbF + s * 8, eB = mbE + s * 8;

        if (kt < KT - 2) cp_wait2(); else if (kt == KT - 2) cp_wait1(); else cp_wait0();
        __syncwarp();
        if (lane == 0) mbar_arrive(fB);
        mbar_wait(fB, ph);

        uint32_t S = base + s * G2_STG;
#pragma unroll
        for (int ks = 0; ks < 4; ks++) {
            uint32_t a[4][4];
#pragma unroll
            for (int mi = 0; mi < 4; mi++)
                LDSM4(a[mi][0], a[mi][1], a[mi][2], a[mi][3], S + aoff[mi] + ks * 32);
#pragma unroll
            for (int p = 0; p < 2; p++) {
                uint32_t b4[4];
                LDSM4(b4[0], b4[1], b4[2], b4[3], S + boff[p] + ks * 32);
#pragma unroll
                for (int mi = 0; mi < 4; mi++) {
                    hmma(acc[mi][2 * p],     a[mi], b4 + 0);
                    hmma(acc[mi][2 * p + 1], a[mi], b4 + 2);
                }
            }
        }
        __syncwarp();
        if (lane == 0) mbar_arrive(eB);

        if (kt + NSTAGE < KT) {
            mbar_wait(eB, ph);
            issue(s, kt + NSTAGE);
        }
    }

#pragma unroll
    for (int mi = 0; mi < 4; mi++)
#pragma unroll
        for (int ni = 0; ni < 4; ni++)
#pragma unroll
            for (int rr = 0; rr < 4; rr++) {
                int rl = wm + mi * 16 + (lane >> 2) + ((rr >= 2) ? 8 : 0);
                int tok = stok[rl];
                if (tok < 0) continue;
                int col = n0 + wn + ni * 8 + 2 * (lane & 3) + (rr & 1);
                atomicAdd(out + (size_t)tok * D_MODEL + col, swt[rl] * acc[mi][ni][rr]);
            }
}

// ---------------- launch: forked-stream graph with row-half overlap ------------
extern "C" void kernel_launch(void* const* d_in, const int* in_sizes, int n_in,
                              void* d_out, int out_size) {
    const float* x  = (const float*)d_in[0];
    const float* rw = (const float*)d_in[1];
    const float* rb = (const float*)d_in[2];
    const float* wg = (const float*)d_in[3];
    const float* wu = (const float*)d_in[4];
    const float* wd = (const float*)d_in[5];
    float* out = (float*)d_out;
    (void)in_sizes; (void)n_in; (void)out_size;

    static cudaStream_t s1 = nullptr, s2 = nullptr;
    static cudaEvent_t evFork = nullptr, evGU = nullptr, evWd = nullptr;
    static cudaEvent_t evG1R0 = nullptr, evG2R0 = nullptr;
    if (!s1) {
        cudaStreamCreateWithFlags(&s1, cudaStreamNonBlocking);
        cudaStreamCreateWithFlags(&s2, cudaStreamNonBlocking);
        cudaEventCreateWithFlags(&evFork, cudaEventDisableTiming);
        cudaEventCreateWithFlags(&evGU,   cudaEventDisableTiming);
        cudaEventCreateWithFlags(&evWd,   cudaEventDisableTiming);
        cudaEventCreateWithFlags(&evG1R0, cudaEventDisableTiming);
        cudaEventCreateWithFlags(&evG2R0, cudaEventDisableTiming);
        cudaFuncSetAttribute(gemm1_kernel, cudaFuncAttributeMaxDynamicSharedMemorySize, G1_SMEM);
        cudaFuncSetAttribute(gemm2_kernel, cudaFuncAttributeMaxDynamicSharedMemorySize, G2_SMEM);
    }

    // fork s1 (weight prep) and s2 (early gemm2) off stream 0
    cudaEventRecord(evFork, 0);
    cudaStreamWaitEvent(s1, evFork, 0);
    cudaStreamWaitEvent(s2, evFork, 0);

    prep_wgu_kernel<<<32768, 256, 0, s1>>>(wg, wu);
    cudaEventRecord(evGU, s1);
    prep_wd_kernel<<<16384, 256, 0, s1>>>(wd);
    cudaEventRecord(evWd, s1);

    prep_x_kernel<<<1024, 256>>>(x, rw, rb, out);     // stream 0
    offsfill_kernel<<<1, 1024>>>();

    cudaStreamWaitEvent(0, evGU, 0);
    gemm1_kernel<<<dim3(NTILES_H, DFF / 128), 256, G1_SMEM>>>(0);        // rows 0-51
    cudaEventRecord(evG1R0, 0);
    gemm1_kernel<<<dim3(NTILES_H, DFF / 128), 256, G1_SMEM>>>(NTILES_H); // rows 52-103

    // early gemm2 on s2: overlaps gemm1 second half
    cudaStreamWaitEvent(s2, evG1R0, 0);
    cudaStreamWaitEvent(s2, evWd, 0);
    gemm2_kernel<<<dim3(NTILES_H, D_MODEL / 128), 256, G2_SMEM, s2>>>(out, 0);
    cudaEventRecord(evG2R0, s2);

    // remaining gemm2 on stream 0 (after gemm1_R1, implicit order)
    cudaStreamWaitEvent(0, evWd, 0);
    gemm2_kernel<<<dim3(NTILES_H, D_MODEL / 128), 256, G2_SMEM>>>(out, NTILES_H);
    cudaStreamWaitEvent(0, evG2R0, 0);   // join s2 back into the graph
}